// round 11
// baseline (speedup 1.0000x reference)
#include <cuda_runtime.h>
#include <cuda_bf16.h>
#include <math.h>
#include <stdint.h>

#define BATCH 2
#define TLEN  2048
#define EMB   1024
#define NHEAD 16
#define HDIM  64
#define MROWS (BATCH*TLEN)   /* 4096 */
#define HID   (4*EMB)        /* 4096 */

typedef __nv_bfloat16 bf16;

// ---- scratch (device globals; no allocation allowed) ----
__device__ float g_qkv[(size_t)MROWS * 3 * EMB];
__device__ float g_x1 [(size_t)MROWS * EMB];
__device__ bf16  g_lnh[(size_t)MROWS * EMB];              // LN split hi plane
__device__ bf16  g_lnl[(size_t)MROWS * EMB];              // LN split lo plane
__device__ bf16  g_whq[(size_t)3145728];                  // w_qkv hi plane [3E,E]
__device__ bf16  g_wlq[(size_t)3145728];                  // w_qkv lo plane
__device__ bf16  g_whf[(size_t)4194304];                  // w_fc hi plane [H,E]
__device__ bf16  g_wlf[(size_t)4194304];                  // w_fc lo plane
__device__ bf16  g_whp[(size_t)4194304];                  // w_proj hi plane [E,H]
__device__ bf16  g_wlp[(size_t)4194304];                  // w_proj lo plane
__device__ bf16  g_a3h[(size_t)MROWS * HID];              // fc out hi plane
__device__ bf16  g_a3l[(size_t)MROWS * HID];              // fc out lo plane
__device__ bf16  g_q3 [(size_t)32 * TLEN * 192];          // Q split [bh,t,192]
__device__ bf16  g_k3 [(size_t)32 * TLEN * 192];          // K split [bh,t,192]
__device__ bf16  g_v3 [(size_t)32 * HDIM * 4096];         // V planes [bh,dv, tile:64vh|64vl]

__device__ __forceinline__ uint32_t smem_u32(const void* p) {
    uint32_t a;
    asm("{ .reg .u64 t; cvta.to.shared.u64 t, %1; cvt.u32.u64 %0, t; }" : "=r"(a) : "l"(p));
    return a;
}
__device__ __forceinline__ void cp16(uint32_t saddr, const void* gaddr) {
    asm volatile("cp.async.cg.shared.global [%0], [%1], 16;" :: "r"(saddr), "l"(gaddr) : "memory");
}
__device__ __forceinline__ void ldsm_x4(uint32_t* r, uint32_t addr) {
    asm volatile("ldmatrix.sync.aligned.m8n8.x4.shared.b16 {%0,%1,%2,%3}, [%4];"
                 : "=r"(r[0]), "=r"(r[1]), "=r"(r[2]), "=r"(r[3]) : "r"(addr));
}
__device__ __forceinline__ void mma16816(float* c, const uint32_t* a, uint32_t b0, uint32_t b1) {
    asm volatile(
        "mma.sync.aligned.m16n8k16.row.col.f32.bf16.bf16.f32 "
        "{%0,%1,%2,%3}, {%4,%5,%6,%7}, {%8,%9}, {%0,%1,%2,%3};"
        : "+f"(c[0]), "+f"(c[1]), "+f"(c[2]), "+f"(c[3])
        : "r"(a[0]), "r"(a[1]), "r"(a[2]), "r"(a[3]), "r"(b0), "r"(b1));
}
__device__ __forceinline__ uint32_t pk2(bf16 a, bf16 b) {
    return (uint32_t)__bfloat16_as_ushort(a) | ((uint32_t)__bfloat16_as_ushort(b) << 16);
}
__device__ __forceinline__ void split2(float v, bf16& hi, bf16& lo) {
    hi = __float2bfloat16(v);
    lo = __float2bfloat16(v - __bfloat162float(hi));
}
__device__ __forceinline__ bf16 hi_bf(float v) { return __float2bfloat16(v); }
__device__ __forceinline__ bf16 lo_bf(float v) {
    bf16 h = __float2bfloat16(v);
    return __float2bfloat16(v - __bfloat162float(h));
}

// ------------------------------------------------------------------
// Weight conversion: W[K,N] f32 -> hi/lo planes [N,K] (transposed)
// ------------------------------------------------------------------
__global__ __launch_bounds__(1024) void convert_wt(
    const float* __restrict__ W, bf16* __restrict__ wh, bf16* __restrict__ wl,
    int K, int N)
{
    __shared__ float t[32][33];
    int tx = threadIdx.x, ty = threadIdx.y;
    int k0 = blockIdx.x * 32, n0 = blockIdx.y * 32;
    t[ty][tx] = W[(size_t)(k0 + ty) * N + n0 + tx];
    __syncthreads();
    float w = t[tx][ty];               // k = k0+tx, n = n0+ty
    bf16 hi, lo; split2(w, hi, lo);
    size_t o = (size_t)(n0 + ty) * K + (k0 + tx);
    wh[o] = hi; wl[o] = lo;
}

// ------------------------------------------------------------------
// LayerNorm fused with activation split -> hi/lo planes [M,K]
// ------------------------------------------------------------------
__global__ __launch_bounds__(256) void ln_split(
    const float* __restrict__ x, const float* __restrict__ scale,
    const float* __restrict__ shift, bf16* __restrict__ lnh, bf16* __restrict__ lnl)
{
    int row = blockIdx.x;
    int t = threadIdx.x;
    const float4* xr = (const float4*)(x + (size_t)row * EMB);
    float4 v = xr[t];
    float s  = v.x + v.y + v.z + v.w;
    float sq = v.x*v.x + v.y*v.y + v.z*v.z + v.w*v.w;

    __shared__ float red[16];
    __shared__ float mv[2];
    #pragma unroll
    for (int o = 16; o > 0; o >>= 1) {
        s  += __shfl_xor_sync(0xffffffffu, s,  o);
        sq += __shfl_xor_sync(0xffffffffu, sq, o);
    }
    if ((t & 31) == 0) { red[t >> 5] = s; red[8 + (t >> 5)] = sq; }
    __syncthreads();
    if (t == 0) {
        float S = 0.f, SQ = 0.f;
        #pragma unroll
        for (int i = 0; i < 8; i++) { S += red[i]; SQ += red[8 + i]; }
        float mean = S * (1.0f / EMB);
        float var  = SQ * (1.0f / EMB) - mean * mean;
        mv[0] = mean; mv[1] = rsqrtf(var + 1e-5f);
    }
    __syncthreads();
    float mean = mv[0], inv = mv[1];
    float4 sc = ((const float4*)scale)[t];
    float4 sh = ((const float4*)shift)[t];
    float o0 = (v.x - mean) * inv * sc.x + sh.x;
    float o1 = (v.y - mean) * inv * sc.y + sh.y;
    float o2 = (v.z - mean) * inv * sc.z + sh.z;
    float o3 = (v.w - mean) * inv * sc.w + sh.w;
    bf16 h0,l0,h1,l1,h2,l2,h3,l3;
    split2(o0,h0,l0); split2(o1,h1,l1); split2(o2,h2,l2); split2(o3,h3,l3);
    uint32_t* ph = (uint32_t*)(lnh + (size_t)row * EMB) + 2 * t;
    ph[0] = pk2(h0,h1); ph[1] = pk2(h2,h3);
    uint32_t* pl = (uint32_t*)(lnl + (size_t)row * EMB) + 2 * t;
    pl[0] = pk2(l0,l1); pl[1] = pk2(l2,l3);
}

// ------------------------------------------------------------------
// prep_attn: Q (A pattern), K (B pattern) interleaved; V -> hi/lo planes
// ------------------------------------------------------------------
__global__ __launch_bounds__(256) void prep_attn(
    const float* __restrict__ qkv, bf16* __restrict__ q3,
    bf16* __restrict__ k3, bf16* __restrict__ v3)
{
    __shared__ float vt[64][65];
    int bh = blockIdx.y;
    int tt = blockIdx.x;
    int b = bh >> 4, h = bh & 15;
    int t0 = tt * 64;
    int tid = threadIdx.x;
    int r = tid >> 2, cc = (tid & 3) * 16;
    const float* base = qkv + ((size_t)(b * TLEN + t0 + r)) * 3072 + h * 64;

    float vq[16], vk[16], vv[16];
    #pragma unroll
    for (int j = 0; j < 4; j++) {
        *(float4*)(vq + 4 * j) = *(const float4*)(base + cc + 4 * j);
        *(float4*)(vk + 4 * j) = *(const float4*)(base + 1024 + cc + 4 * j);
        *(float4*)(vv + 4 * j) = *(const float4*)(base + 2048 + cc + 4 * j);
    }

    // Q: A pattern (hi,hi,lo)
    {
        uint32_t ob[24];
        #pragma unroll
        for (int j = 0; j < 16; j += 2) {
            bf16 a0,b0,a1,b1;
            split2(vq[j], a0, b0); split2(vq[j+1], a1, b1);
            int k = 3 * (j >> 1);
            ob[k]     = pk2(a0,a0);
            ob[k + 1] = pk2(b0,a1);
            ob[k + 2] = pk2(a1,b1);
        }
        uint4* d = (uint4*)(q3 + ((size_t)bh * TLEN + t0 + r) * 192 + 3 * cc);
        #pragma unroll
        for (int j = 0; j < 6; j++) d[j] = ((uint4*)ob)[j];
    }
    // K: B pattern (hi,lo,hi)
    {
        uint32_t ob[24];
        #pragma unroll
        for (int j = 0; j < 16; j += 2) {
            bf16 a0,b0,a1,b1;
            split2(vk[j], a0, b0); split2(vk[j+1], a1, b1);
            int k = 3 * (j >> 1);
            ob[k]     = pk2(a0,b0);
            ob[k + 1] = pk2(a0,a1);
            ob[k + 2] = pk2(b1,a1);
        }
        uint4* d = (uint4*)(k3 + ((size_t)bh * TLEN + t0 + r) * 192 + 3 * cc);
        #pragma unroll
        for (int j = 0; j < 6; j++) d[j] = ((uint4*)ob)[j];
    }
    // V transpose via smem
    #pragma unroll
    for (int j = 0; j < 16; j++) vt[cc + j][r] = vv[j];
    __syncthreads();
    {
        uint32_t oh[8], ol[8];
        #pragma unroll
        for (int j = 0; j < 16; j += 2) {
            bf16 a0,b0,a1,b1;
            split2(vt[r][cc + j], a0, b0); split2(vt[r][cc + j + 1], a1, b1);
            oh[j >> 1] = pk2(a0, a1);
            ol[j >> 1] = pk2(b0, b1);
        }
        bf16* vrow = v3 + ((size_t)bh * 64 + r) * 4096 + (size_t)tt * 128;
        uint4* dh = (uint4*)(vrow + cc);
        dh[0] = ((uint4*)oh)[0]; dh[1] = ((uint4*)oh)[1];
        uint4* dl = (uint4*)(vrow + 64 + cc);
        dl[0] = ((uint4*)ol)[0]; dl[1] = ((uint4*)ol)[1];
    }
}

// ------------------------------------------------------------------
// HMMA GEMM, plane-segmented triple split:
//   C = Ah.Bh^T + Ah.Bl^T + Al.Bh^T  (+bias, +relu, +res | split-out planes)
// BM=128 BN=128 BK=64, 3-stage cp.async, 8 warps (2x4), warp 64x32, occ 2.
// ------------------------------------------------------------------
#define ROWB   144
#define TILEB  (128*ROWB)      /* 18432 */
#define STAGEB (2*TILEB)       /* 36864 */
#define GSMEM  (3*STAGEB)      /* 110592 */

template<bool RELU, bool HASRES, bool WSPLIT>
__global__ __launch_bounds__(256, 2)
void gemm_tc(const bf16* __restrict__ Ah, const bf16* __restrict__ Al,
             const bf16* __restrict__ Bh, const bf16* __restrict__ Bl,
             const float* __restrict__ bias, const float* __restrict__ res,
             float* __restrict__ C, bf16* __restrict__ C3h, bf16* __restrict__ C3l,
             int N, int K)
{
    extern __shared__ __align__(128) unsigned char smem[];
    uint32_t sb = smem_u32(smem);
    int tid = threadIdx.x, w = tid >> 5, l = tid & 31;
    int wm = w >> 2, wn = w & 3;
    int m0 = blockIdx.y * 128, n0 = blockIdx.x * 128;
    int KC = K >> 6;
    int NCH = 3 * KC;

    const bf16* Ahb = Ah + (size_t)m0 * K;
    const bf16* Alb = Al + (size_t)m0 * K;
    const bf16* Bhb = Bh + (size_t)n0 * K;
    const bf16* Blb = Bl + (size_t)n0 * K;

    int lrow[4], lch[4];
    #pragma unroll
    for (int i = 0; i < 4; i++) {
        int idx = tid + i * 256;
        lrow[i] = idx >> 3; lch[i] = idx & 7;
    }

    uint32_t aBase = sb + (uint32_t)((wm * 64 + ((l >> 3) & 1) * 8 + (l & 7)) * ROWB + (l >> 4) * 16);
    uint32_t bBase = sb + TILEB + (uint32_t)((wn * 32 + (l >> 4) * 8 + (l & 7)) * ROWB + ((l >> 3) & 1) * 16);

    float acc[4][4][4];
    #pragma unroll
    for (int i = 0; i < 4; i++)
        #pragma unroll
        for (int j = 0; j < 4; j++)
            #pragma unroll
            for (int q = 0; q < 4; q++) acc[i][j][q] = 0.f;

    // prologue: chunks 0,1 (both in segment 0 since KC >= 16)
    #pragma unroll
    for (int s = 0; s < 2; s++) {
        size_t kc = (size_t)s * 64;
        #pragma unroll
        for (int i = 0; i < 4; i++) {
            uint32_t so = (uint32_t)(s * STAGEB + lrow[i] * ROWB + lch[i] * 16);
            cp16(sb + so,         Ahb + (size_t)lrow[i] * K + kc + lch[i] * 8);
            cp16(sb + TILEB + so, Bhb + (size_t)lrow[i] * K + kc + lch[i] * 8);
        }
        asm volatile("cp.async.commit_group;" ::: "memory");
    }

    for (int c = 0; c < NCH; c++) {
        asm volatile("cp.async.wait_group 1;" ::: "memory");
        __syncthreads();
        int nc = c + 2;
        if (nc < NCH) {
            int buf = nc % 3;
            int seg = (nc >= KC) + (nc >= 2 * KC);
            int kk = nc - seg * KC;
            const bf16* Asrc = (seg == 2) ? Alb : Ahb;
            const bf16* Bsrc = (seg == 1) ? Blb : Bhb;
            size_t kc = (size_t)kk * 64;
            #pragma unroll
            for (int i = 0; i < 4; i++) {
                uint32_t so = (uint32_t)(buf * STAGEB + lrow[i] * ROWB + lch[i] * 16);
                cp16(sb + so,         Asrc + (size_t)lrow[i] * K + kc + lch[i] * 8);
                cp16(sb + TILEB + so, Bsrc + (size_t)lrow[i] * K + kc + lch[i] * 8);
            }
        }
        asm volatile("cp.async.commit_group;" ::: "memory");

        uint32_t as0 = aBase + (uint32_t)((c % 3) * STAGEB);
        uint32_t bs0 = bBase + (uint32_t)((c % 3) * STAGEB);
        #pragma unroll
        for (int ks = 0; ks < 4; ks++) {
            uint32_t ar[4][4], br[2][4];
            #pragma unroll
            for (int mt = 0; mt < 4; mt++)
                ldsm_x4(ar[mt], as0 + mt * (16 * ROWB) + ks * 32);
            #pragma unroll
            for (int p = 0; p < 2; p++)
                ldsm_x4(br[p], bs0 + p * (16 * ROWB) + ks * 32);
            #pragma unroll
            for (int mt = 0; mt < 4; mt++) {
                #pragma unroll
                for (int nt = 0; nt < 4; nt++) {
                    int p = nt >> 1, hh = (nt & 1) * 2;
                    mma16816(acc[mt][nt], ar[mt], br[p][hh], br[p][hh + 1]);
                }
            }
        }
    }

    // epilogue
    int g = l >> 2, t4 = l & 3;
    #pragma unroll
    for (int mt = 0; mt < 4; mt++) {
        int row0 = m0 + wm * 64 + mt * 16 + g;
        #pragma unroll
        for (int nt = 0; nt < 4; nt++) {
            int col = n0 + wn * 32 + nt * 8 + t4 * 2;
            float2 bv = *(const float2*)(bias + col);
            float v0 = acc[mt][nt][0] + bv.x;
            float v1 = acc[mt][nt][1] + bv.y;
            float v2 = acc[mt][nt][2] + bv.x;
            float v3 = acc[mt][nt][3] + bv.y;
            if (RELU) {
                v0 = fmaxf(v0, 0.f); v1 = fmaxf(v1, 0.f);
                v2 = fmaxf(v2, 0.f); v3 = fmaxf(v3, 0.f);
            }
            if (WSPLIT) {
                bf16 h0,l0,h1,l1;
                split2(v0,h0,l0); split2(v1,h1,l1);
                *(uint32_t*)(C3h + (size_t)row0 * N + col) = pk2(h0,h1);
                *(uint32_t*)(C3l + (size_t)row0 * N + col) = pk2(l0,l1);
                split2(v2,h0,l0); split2(v3,h1,l1);
                *(uint32_t*)(C3h + (size_t)(row0 + 8) * N + col) = pk2(h0,h1);
                *(uint32_t*)(C3l + (size_t)(row0 + 8) * N + col) = pk2(l0,l1);
            } else {
                if (HASRES) {
                    float2 r1 = *(const float2*)(res + (size_t)row0 * N + col);
                    float2 r2 = *(const float2*)(res + (size_t)(row0 + 8) * N + col);
                    v0 += r1.x; v1 += r1.y; v2 += r2.x; v3 += r2.y;
                }
                *(float2*)(C + (size_t)row0 * N + col)       = make_float2(v0, v1);
                *(float2*)(C + (size_t)(row0 + 8) * N + col) = make_float2(v2, v3);
            }
        }
    }
}

// ------------------------------------------------------------------
// HMMA flash attention (causal), triple-split bf16, registers-direct P.
// 1-D grid, GLOBAL heavy-first ordering: qi = 15 - bid/32, bh = bid%32.
// ------------------------------------------------------------------
#define LDROW 400
#define VROW  272
#define AQ_OFF   0u
#define AK_OFF   51200u
#define AV_OFF   102400u
#define ASMEM    137216

__global__ __launch_bounds__(256) void attn_hmma(
    const bf16* __restrict__ q3, const bf16* __restrict__ k3,
    const bf16* __restrict__ v3, const float* __restrict__ x,
    float* __restrict__ x1)
{
    extern __shared__ __align__(128) unsigned char sm[];
    uint32_t sb = smem_u32(sm);
    int tid = threadIdx.x, w = tid >> 5, l = tid & 31;
    int g = l >> 2, t4 = l & 3;
    int bid = blockIdx.x;
    int bh = bid & 31;
    int qi = (TLEN / 128 - 1) - (bid >> 5);   // heavy tiles launch first, globally
    int b = bh >> 4, h = bh & 15;
    int q0 = qi * 128;
    int ktn = 2 * qi + 2;

    const bf16* qb = q3 + ((size_t)bh * TLEN + q0) * 192;
    const bf16* kb = k3 + (size_t)bh * TLEN * 192;
    const bf16* vb = v3 + (size_t)bh * 64 * 4096;

    // Q tile: 128 rows x 24 chunks
    for (int i = tid; i < 3072; i += 256) {
        int r = i / 24, c = i % 24;
        cp16(sb + AQ_OFF + r * LDROW + c * 16, qb + (size_t)r * 192 + c * 8);
    }
    asm volatile("cp.async.commit_group;" ::: "memory");
    // KV tile 0 into buf 0
    for (int i = tid; i < 1536; i += 256) {
        int r = i / 24, c = i % 24;
        cp16(sb + AK_OFF + r * LDROW + c * 16, kb + (size_t)r * 192 + c * 8);
    }
    for (int i = tid; i < 1024; i += 256) {
        int r = i >> 4, c = i & 15;
        cp16(sb + AV_OFF + r * VROW + c * 16, vb + (size_t)r * 4096 + c * 8);
    }
    asm volatile("cp.async.commit_group;" ::: "memory");

    uint32_t rowPartA = (uint32_t)((16 * w + ((l >> 3) & 1) * 8 + (l & 7)) * LDROW + (l >> 4) * 16);
    uint32_t aQ = sb + AQ_OFF + rowPartA;
    uint32_t bPartK = (uint32_t)(((l >> 4) * 8 + (l & 7)) * LDROW + ((l >> 3) & 1) * 16);
    uint32_t bPartV = (uint32_t)(((l >> 4) * 8 + (l & 7)) * VROW + ((l >> 3) & 1) * 16);

    float m_[2] = {-1e30f, -1e30f};
    float l_[2] = {0.f, 0.f};
    float oacc[8][4];
    #pragma unroll
    for (int nt = 0; nt < 8; nt++)
        #pragma unroll
        for (int q = 0; q < 4; q++) oacc[nt][q] = 0.f;

    for (int kt = 0; kt < ktn; kt++) {
        asm volatile("cp.async.wait_group 0;" ::: "memory");
        __syncthreads();
        if (kt + 1 < ktn) {
            uint32_t kboff = ((kt + 1) & 1) * 25600u;
            uint32_t vboff = ((kt + 1) & 1) * 17408u;
            for (int i = tid; i < 1536; i += 256) {
                int r = i / 24, c = i % 24;
                cp16(sb + AK_OFF + kboff + r * LDROW + c * 16,
                     kb + ((size_t)(kt + 1) * 64 + r) * 192 + c * 8);
            }
            for (int i = tid; i < 1024; i += 256) {
                int r = i >> 4, c = i & 15;
                cp16(sb + AV_OFF + vboff + r * VROW + c * 16,
                     vb + (size_t)r * 4096 + (size_t)(kt + 1) * 128 + c * 8);
            }
        }
        asm volatile("cp.async.commit_group;" ::: "memory");

        uint32_t bK = sb + AK_OFF + (kt & 1) * 25600u + bPartK;
        uint32_t bV = sb + AV_OFF + (kt & 1) * 17408u + bPartV;

        // S = Q K^T
        float sacc[8][4];
        #pragma unroll
        for (int nt = 0; nt < 8; nt++)
            #pragma unroll
            for (int q = 0; q < 4; q++) sacc[nt][q] = 0.f;
        #pragma unroll
        for (int ks = 0; ks < 12; ks++) {
            uint32_t ar[4], br[4][4];
            ldsm_x4(ar, aQ + ks * 32);
            #pragma unroll
            for (int p = 0; p < 4; p++)
                ldsm_x4(br[p], bK + p * (16 * LDROW) + ks * 32);
            #pragma unroll
            for (int nt = 0; nt < 8; nt++)
                mma16816(sacc[nt], ar, br[nt >> 1][(nt & 1) * 2], br[nt >> 1][(nt & 1) * 2 + 1]);
        }

        int k0 = kt * 64;
        if (k0 + 63 > q0) {
            int r0 = q0 + 16 * w + g, r1 = r0 + 8;
            #pragma unroll
            for (int nt = 0; nt < 8; nt++) {
                int c0 = k0 + nt * 8 + t4 * 2;
                sacc[nt][0] = (c0     > r0) ? -1e30f : sacc[nt][0] * 0.125f;
                sacc[nt][1] = (c0 + 1 > r0) ? -1e30f : sacc[nt][1] * 0.125f;
                sacc[nt][2] = (c0     > r1) ? -1e30f : sacc[nt][2] * 0.125f;
                sacc[nt][3] = (c0 + 1 > r1) ? -1e30f : sacc[nt][3] * 0.125f;
            }
        } else {
            #pragma unroll
            for (int nt = 0; nt < 8; nt++)
                #pragma unroll
                for (int q = 0; q < 4; q++) sacc[nt][q] *= 0.125f;
        }

        // online softmax per row-half
        #pragma unroll
        for (int h2 = 0; h2 < 2; h2++) {
            float mx = -1e30f;
            #pragma unroll
            for (int nt = 0; nt < 8; nt++)
                mx = fmaxf(mx, fmaxf(sacc[nt][h2 * 2], sacc[nt][h2 * 2 + 1]));
            mx = fmaxf(mx, __shfl_xor_sync(0xffffffffu, mx, 1));
            mx = fmaxf(mx, __shfl_xor_sync(0xffffffffu, mx, 2));
            float mn = fmaxf(m_[h2], mx);
            float al = __expf(m_[h2] - mn);
            float sum = 0.f;
            #pragma unroll
            for (int nt = 0; nt < 8; nt++) {
                float p0 = __expf(sacc[nt][h2 * 2]     - mn);
                float p1 = __expf(sacc[nt][h2 * 2 + 1] - mn);
                sacc[nt][h2 * 2] = p0; sacc[nt][h2 * 2 + 1] = p1;
                sum += p0 + p1;
            }
            sum += __shfl_xor_sync(0xffffffffu, sum, 1);
            sum += __shfl_xor_sync(0xffffffffu, sum, 2);
            l_[h2] = l_[h2] * al + sum;
            m_[h2] = mn;
            #pragma unroll
            for (int nt = 0; nt < 8; nt++) {
                oacc[nt][h2 * 2]     *= al;
                oacc[nt][h2 * 2 + 1] *= al;
            }
        }

        // O += P V  — P direct from registers (C-frag == A-frag layout)
        #pragma unroll
        for (int kbk = 0; kbk < 4; kbk++) {
            uint32_t aH[4], aL[4];
            aH[0] = pk2(hi_bf(sacc[2*kbk][0]),   hi_bf(sacc[2*kbk][1]));
            aH[1] = pk2(hi_bf(sacc[2*kbk][2]),   hi_bf(sacc[2*kbk][3]));
            aH[2] = pk2(hi_bf(sacc[2*kbk+1][0]), hi_bf(sacc[2*kbk+1][1]));
            aH[3] = pk2(hi_bf(sacc[2*kbk+1][2]), hi_bf(sacc[2*kbk+1][3]));
            aL[0] = pk2(lo_bf(sacc[2*kbk][0]),   lo_bf(sacc[2*kbk][1]));
            aL[1] = pk2(lo_bf(sacc[2*kbk][2]),   lo_bf(sacc[2*kbk][3]));
            aL[2] = pk2(lo_bf(sacc[2*kbk+1][0]), lo_bf(sacc[2*kbk+1][1]));
            aL[3] = pk2(lo_bf(sacc[2*kbk+1][2]), lo_bf(sacc[2*kbk+1][3]));

            uint32_t vh[4][4], vl[4][4];
            #pragma unroll
            for (int p = 0; p < 4; p++) {
                ldsm_x4(vh[p], bV + p * (16 * VROW) + kbk * 32);
                ldsm_x4(vl[p], bV + 128 + p * (16 * VROW) + kbk * 32);
            }
            #pragma unroll
            for (int nt = 0; nt < 8; nt++) {
                int p = nt >> 1, hh = (nt & 1) * 2;
                mma16816(oacc[nt], aH, vh[p][hh], vh[p][hh + 1]);
                mma16816(oacc[nt], aH, vl[p][hh], vl[p][hh + 1]);
                mma16816(oacc[nt], aL, vh[p][hh], vh[p][hh + 1]);
            }
        }
    }

    // epilogue: y/l + residual x -> x1
    #pragma unroll
    for (int h2 = 0; h2 < 2; h2++) {
        float inv = 1.f / l_[h2];
        int row = b * TLEN + q0 + 16 * w + g + 8 * h2;
        const float* xr = x  + (size_t)row * EMB + h * 64;
        float*       xo = x1 + (size_t)row * EMB + h * 64;
        #pragma unroll
        for (int nt = 0; nt < 8; nt++) {
            int c = nt * 8 + t4 * 2;
            float2 xv = *(const float2*)(xr + c);
            float2 yv;
            yv.x = oacc[nt][h2 * 2]     * inv + xv.x;
            yv.y = oacc[nt][h2 * 2 + 1] * inv + xv.y;
            *(float2*)(xo + c) = yv;
        }
    }
}

// ------------------------------------------------------------------
extern "C" void kernel_launch(void* const* d_in, const int* in_sizes, int n_in,
                              void* d_out, int out_size)
{
    const float* x      = (const float*)d_in[0];
    const float* ln1s   = (const float*)d_in[1];
    const float* ln1b   = (const float*)d_in[2];
    const float* w_qkv  = (const float*)d_in[3];
    const float* b_qkv  = (const float*)d_in[4];
    const float* ln2s   = (const float*)d_in[5];
    const float* ln2b   = (const float*)d_in[6];
    const float* w_fc   = (const float*)d_in[7];
    const float* b_fc   = (const float*)d_in[8];
    const float* w_proj = (const float*)d_in[9];
    const float* b_proj = (const float*)d_in[10];
    float* out = (float*)d_out;

    float *qkv, *x1;
    bf16 *lnh, *lnl, *whq, *wlq, *whf, *wlf, *whp, *wlp, *a3h, *a3l, *q3, *k3, *v3;
    cudaGetSymbolAddress((void**)&qkv, g_qkv);
    cudaGetSymbolAddress((void**)&x1,  g_x1);
    cudaGetSymbolAddress((void**)&lnh, g_lnh);
    cudaGetSymbolAddress((void**)&lnl, g_lnl);
    cudaGetSymbolAddress((void**)&whq, g_whq);
    cudaGetSymbolAddress((void**)&wlq, g_wlq);
    cudaGetSymbolAddress((void**)&whf, g_whf);
    cudaGetSymbolAddress((void**)&wlf, g_wlf);
    cudaGetSymbolAddress((void**)&whp, g_whp);
    cudaGetSymbolAddress((void**)&wlp, g_wlp);
    cudaGetSymbolAddress((void**)&a3h, g_a3h);
    cudaGetSymbolAddress((void**)&a3l, g_a3l);
    cudaGetSymbolAddress((void**)&q3,  g_q3);
    cudaGetSymbolAddress((void**)&k3,  g_k3);
    cudaGetSymbolAddress((void**)&v3,  g_v3);

    cudaFuncSetAttribute(attn_hmma, cudaFuncAttributeMaxDynamicSharedMemorySize, ASMEM);
    cudaFuncSetAttribute(gemm_tc<false,false,false>, cudaFuncAttributeMaxDynamicSharedMemorySize, GSMEM);
    cudaFuncSetAttribute(gemm_tc<true,false,true>,   cudaFuncAttributeMaxDynamicSharedMemorySize, GSMEM);
    cudaFuncSetAttribute(gemm_tc<false,true,false>,  cudaFuncAttributeMaxDynamicSharedMemorySize, GSMEM);

    // side stream + fork events (created once, on the first/correctness call;
    // identical captured work every call)
    static cudaStream_t s1 = nullptr;
    static cudaEvent_t evFork = nullptr, evQ = nullptr, evF = nullptr, evP = nullptr;
    if (s1 == nullptr) {
        cudaStreamCreateWithFlags(&s1, cudaStreamNonBlocking);
        cudaEventCreateWithFlags(&evFork, cudaEventDisableTiming);
        cudaEventCreateWithFlags(&evQ,    cudaEventDisableTiming);
        cudaEventCreateWithFlags(&evF,    cudaEventDisableTiming);
        cudaEventCreateWithFlags(&evP,    cudaEventDisableTiming);
    }

    // fork: weight conversions run on s1, overlapping LN/GEMM/attention
    cudaEventRecord(evFork, 0);
    cudaStreamWaitEvent(s1, evFork, 0);
    convert_wt<<<dim3(EMB / 32, 3 * EMB / 32), dim3(32, 32), 0, s1>>>(w_qkv, whq, wlq, EMB, 3 * EMB);
    cudaEventRecord(evQ, s1);
    convert_wt<<<dim3(EMB / 32, HID / 32), dim3(32, 32), 0, s1>>>(w_fc, whf, wlf, EMB, HID);
    cudaEventRecord(evF, s1);
    convert_wt<<<dim3(HID / 32, EMB / 32), dim3(32, 32), 0, s1>>>(w_proj, whp, wlp, HID, EMB);
    cudaEventRecord(evP, s1);

    // main stream
    // 1. lnh/lnl = split(LN1(x))   (concurrent with convert(w_qkv))
    ln_split<<<MROWS, 256>>>(x, ln1s, ln1b, lnh, lnl);
    // 2. qkv = ln1 @ w_qkv + b_qkv
    cudaStreamWaitEvent(0, evQ, 0);
    gemm_tc<false,false,false><<<dim3(3 * EMB / 128, MROWS / 128), 256, GSMEM>>>(
        lnh, lnl, whq, wlq, b_qkv, nullptr, qkv, nullptr, nullptr, 3 * EMB, EMB);
    // 3. split/transpose q,k,v
    prep_attn<<<dim3(TLEN / 64, 32), 256>>>(qkv, q3, k3, v3);
    // 4. x1 = x + attention  (fused residual, global heavy-first order)
    attn_hmma<<<(TLEN / 128) * 32, 256, ASMEM>>>(q3, k3, v3, x, x1);
    // 5. lnh/lnl = split(LN2(x1))
    ln_split<<<MROWS, 256>>>(x1, ln2s, ln2b, lnh, lnl);
    // 6. a3h/a3l = split(relu(ln2 @ w_fc + b_fc))
    cudaStreamWaitEvent(0, evF, 0);
    gemm_tc<true,false,true><<<dim3(HID / 128, MROWS / 128), 256, GSMEM>>>(
        lnh, lnl, whf, wlf, b_fc, nullptr, nullptr, a3h, a3l, HID, EMB);
    // 7. out = x1 + fc @ w_proj + b_proj
    cudaStreamWaitEvent(0, evP, 0);
    gemm_tc<false,true,false><<<dim3(EMB / 128, MROWS / 128), 256, GSMEM>>>(
        a3h, a3l, whp, wlp, b_proj, x1, out, nullptr, nullptr, EMB, HID);
}

// round 13
// speedup vs baseline: 1.5326x; 1.5326x over previous
#include <cuda_runtime.h>
#include <cuda_bf16.h>
#include <math.h>
#include <stdint.h>

#define BATCH 2
#define TLEN  2048
#define EMB   1024
#define NHEAD 16
#define HDIM  64
#define MROWS (BATCH*TLEN)   /* 4096 */
#define HID   (4*EMB)        /* 4096 */

typedef __nv_bfloat16 bf16;

// ---- scratch (device globals; no allocation allowed) ----
__device__ float g_qkv[(size_t)MROWS * 3 * EMB];
__device__ float g_x1 [(size_t)MROWS * EMB];
__device__ bf16  g_lnh[(size_t)MROWS * EMB];              // LN split hi plane
__device__ bf16  g_lnl[(size_t)MROWS * EMB];              // LN split lo plane
__device__ bf16  g_wh [(size_t)4194304];                  // weight hi plane [N,K]
__device__ bf16  g_wl [(size_t)4194304];                  // weight lo plane [N,K]
__device__ bf16  g_a3h[(size_t)MROWS * HID];              // fc out hi plane
__device__ bf16  g_a3l[(size_t)MROWS * HID];              // fc out lo plane
__device__ bf16  g_q3 [(size_t)32 * TLEN * 192];          // Q split [bh,t,192]
__device__ bf16  g_k3 [(size_t)32 * TLEN * 192];          // K split [bh,t,192]
__device__ bf16  g_v3 [(size_t)32 * HDIM * 4096];         // V planes [bh,dv, tile:64vh|64vl]

__device__ __forceinline__ uint32_t smem_u32(const void* p) {
    uint32_t a;
    asm("{ .reg .u64 t; cvta.to.shared.u64 t, %1; cvt.u32.u64 %0, t; }" : "=r"(a) : "l"(p));
    return a;
}
__device__ __forceinline__ void cp16(uint32_t saddr, const void* gaddr) {
    asm volatile("cp.async.cg.shared.global [%0], [%1], 16;" :: "r"(saddr), "l"(gaddr) : "memory");
}
__device__ __forceinline__ void ldsm_x4(uint32_t* r, uint32_t addr) {
    asm volatile("ldmatrix.sync.aligned.m8n8.x4.shared.b16 {%0,%1,%2,%3}, [%4];"
                 : "=r"(r[0]), "=r"(r[1]), "=r"(r[2]), "=r"(r[3]) : "r"(addr));
}
__device__ __forceinline__ void mma16816(float* c, const uint32_t* a, uint32_t b0, uint32_t b1) {
    asm volatile(
        "mma.sync.aligned.m16n8k16.row.col.f32.bf16.bf16.f32 "
        "{%0,%1,%2,%3}, {%4,%5,%6,%7}, {%8,%9}, {%0,%1,%2,%3};"
        : "+f"(c[0]), "+f"(c[1]), "+f"(c[2]), "+f"(c[3])
        : "r"(a[0]), "r"(a[1]), "r"(a[2]), "r"(a[3]), "r"(b0), "r"(b1));
}
__device__ __forceinline__ uint32_t pk2(bf16 a, bf16 b) {
    return (uint32_t)__bfloat16_as_ushort(a) | ((uint32_t)__bfloat16_as_ushort(b) << 16);
}
__device__ __forceinline__ void split2(float v, bf16& hi, bf16& lo) {
    hi = __float2bfloat16(v);
    lo = __float2bfloat16(v - __bfloat162float(hi));
}
__device__ __forceinline__ bf16 hi_bf(float v) { return __float2bfloat16(v); }
__device__ __forceinline__ bf16 lo_bf(float v) {
    bf16 h = __float2bfloat16(v);
    return __float2bfloat16(v - __bfloat162float(h));
}

// ------------------------------------------------------------------
// Weight conversion: W[K,N] f32 -> hi/lo planes [N,K] (transposed)
// ------------------------------------------------------------------
__global__ __launch_bounds__(1024) void convert_wt(
    const float* __restrict__ W, bf16* __restrict__ wh, bf16* __restrict__ wl,
    int K, int N)
{
    __shared__ float t[32][33];
    int tx = threadIdx.x, ty = threadIdx.y;
    int k0 = blockIdx.x * 32, n0 = blockIdx.y * 32;
    t[ty][tx] = W[(size_t)(k0 + ty) * N + n0 + tx];
    __syncthreads();
    float w = t[tx][ty];               // k = k0+tx, n = n0+ty
    bf16 hi, lo; split2(w, hi, lo);
    size_t o = (size_t)(n0 + ty) * K + (k0 + tx);
    wh[o] = hi; wl[o] = lo;
}

// ------------------------------------------------------------------
// LayerNorm fused with activation split -> hi/lo planes [M,K]
// ------------------------------------------------------------------
__global__ __launch_bounds__(256) void ln_split(
    const float* __restrict__ x, const float* __restrict__ scale,
    const float* __restrict__ shift, bf16* __restrict__ lnh, bf16* __restrict__ lnl)
{
    int row = blockIdx.x;
    int t = threadIdx.x;
    const float4* xr = (const float4*)(x + (size_t)row * EMB);
    float4 v = xr[t];
    float s  = v.x + v.y + v.z + v.w;
    float sq = v.x*v.x + v.y*v.y + v.z*v.z + v.w*v.w;

    __shared__ float red[16];
    __shared__ float mv[2];
    #pragma unroll
    for (int o = 16; o > 0; o >>= 1) {
        s  += __shfl_xor_sync(0xffffffffu, s,  o);
        sq += __shfl_xor_sync(0xffffffffu, sq, o);
    }
    if ((t & 31) == 0) { red[t >> 5] = s; red[8 + (t >> 5)] = sq; }
    __syncthreads();
    if (t == 0) {
        float S = 0.f, SQ = 0.f;
        #pragma unroll
        for (int i = 0; i < 8; i++) { S += red[i]; SQ += red[8 + i]; }
        float mean = S * (1.0f / EMB);
        float var  = SQ * (1.0f / EMB) - mean * mean;
        mv[0] = mean; mv[1] = rsqrtf(var + 1e-5f);
    }
    __syncthreads();
    float mean = mv[0], inv = mv[1];
    float4 sc = ((const float4*)scale)[t];
    float4 sh = ((const float4*)shift)[t];
    float o0 = (v.x - mean) * inv * sc.x + sh.x;
    float o1 = (v.y - mean) * inv * sc.y + sh.y;
    float o2 = (v.z - mean) * inv * sc.z + sh.z;
    float o3 = (v.w - mean) * inv * sc.w + sh.w;
    bf16 h0,l0,h1,l1,h2,l2,h3,l3;
    split2(o0,h0,l0); split2(o1,h1,l1); split2(o2,h2,l2); split2(o3,h3,l3);
    uint32_t* ph = (uint32_t*)(lnh + (size_t)row * EMB) + 2 * t;
    ph[0] = pk2(h0,h1); ph[1] = pk2(h2,h3);
    uint32_t* pl = (uint32_t*)(lnl + (size_t)row * EMB) + 2 * t;
    pl[0] = pk2(l0,l1); pl[1] = pk2(l2,l3);
}

// ------------------------------------------------------------------
// prep_attn: Q (A pattern), K (B pattern) interleaved; V -> hi/lo planes
// ------------------------------------------------------------------
__global__ __launch_bounds__(256) void prep_attn(
    const float* __restrict__ qkv, bf16* __restrict__ q3,
    bf16* __restrict__ k3, bf16* __restrict__ v3)
{
    __shared__ float vt[64][65];
    int bh = blockIdx.y;
    int tt = blockIdx.x;
    int b = bh >> 4, h = bh & 15;
    int t0 = tt * 64;
    int tid = threadIdx.x;
    int r = tid >> 2, cc = (tid & 3) * 16;
    const float* base = qkv + ((size_t)(b * TLEN + t0 + r)) * 3072 + h * 64;

    float vq[16], vk[16], vv[16];
    #pragma unroll
    for (int j = 0; j < 4; j++) {
        *(float4*)(vq + 4 * j) = *(const float4*)(base + cc + 4 * j);
        *(float4*)(vk + 4 * j) = *(const float4*)(base + 1024 + cc + 4 * j);
        *(float4*)(vv + 4 * j) = *(const float4*)(base + 2048 + cc + 4 * j);
    }

    // Q: A pattern (hi,hi,lo)
    {
        uint32_t ob[24];
        #pragma unroll
        for (int j = 0; j < 16; j += 2) {
            bf16 a0,b0,a1,b1;
            split2(vq[j], a0, b0); split2(vq[j+1], a1, b1);
            int k = 3 * (j >> 1);
            ob[k]     = pk2(a0,a0);
            ob[k + 1] = pk2(b0,a1);
            ob[k + 2] = pk2(a1,b1);
        }
        uint4* d = (uint4*)(q3 + ((size_t)bh * TLEN + t0 + r) * 192 + 3 * cc);
        #pragma unroll
        for (int j = 0; j < 6; j++) d[j] = ((uint4*)ob)[j];
    }
    // K: B pattern (hi,lo,hi)
    {
        uint32_t ob[24];
        #pragma unroll
        for (int j = 0; j < 16; j += 2) {
            bf16 a0,b0,a1,b1;
            split2(vk[j], a0, b0); split2(vk[j+1], a1, b1);
            int k = 3 * (j >> 1);
            ob[k]     = pk2(a0,b0);
            ob[k + 1] = pk2(a0,a1);
            ob[k + 2] = pk2(b1,a1);
        }
        uint4* d = (uint4*)(k3 + ((size_t)bh * TLEN + t0 + r) * 192 + 3 * cc);
        #pragma unroll
        for (int j = 0; j < 6; j++) d[j] = ((uint4*)ob)[j];
    }
    // V transpose via smem
    #pragma unroll
    for (int j = 0; j < 16; j++) vt[cc + j][r] = vv[j];
    __syncthreads();
    {
        uint32_t oh[8], ol[8];
        #pragma unroll
        for (int j = 0; j < 16; j += 2) {
            bf16 a0,b0,a1,b1;
            split2(vt[r][cc + j], a0, b0); split2(vt[r][cc + j + 1], a1, b1);
            oh[j >> 1] = pk2(a0, a1);
            ol[j >> 1] = pk2(b0, b1);
        }
        bf16* vrow = v3 + ((size_t)bh * 64 + r) * 4096 + (size_t)tt * 128;
        uint4* dh = (uint4*)(vrow + cc);
        dh[0] = ((uint4*)oh)[0]; dh[1] = ((uint4*)oh)[1];
        uint4* dl = (uint4*)(vrow + 64 + cc);
        dl[0] = ((uint4*)ol)[0]; dl[1] = ((uint4*)ol)[1];
    }
}

// ------------------------------------------------------------------
// HMMA GEMM, plane-segmented triple split:
//   C = Ah.Bh^T + Ah.Bl^T + Al.Bh^T  (+bias, +relu, +res | split-out planes)
// BM=128 BN=128 BK=64, 3-stage cp.async, 8 warps (2x4), warp 64x32, occ 2.
// ------------------------------------------------------------------
#define ROWB   144
#define TILEB  (128*ROWB)      /* 18432 */
#define STAGEB (2*TILEB)       /* 36864 */
#define GSMEM  (3*STAGEB)      /* 110592 */

template<bool RELU, bool HASRES, bool WSPLIT>
__global__ __launch_bounds__(256, 2)
void gemm_tc(const bf16* __restrict__ Ah, const bf16* __restrict__ Al,
             const bf16* __restrict__ Bh, const bf16* __restrict__ Bl,
             const float* __restrict__ bias, const float* __restrict__ res,
             float* __restrict__ C, bf16* __restrict__ C3h, bf16* __restrict__ C3l,
             int N, int K)
{
    extern __shared__ __align__(128) unsigned char smem[];
    uint32_t sb = smem_u32(smem);
    int tid = threadIdx.x, w = tid >> 5, l = tid & 31;
    int wm = w >> 2, wn = w & 3;
    int m0 = blockIdx.y * 128, n0 = blockIdx.x * 128;
    int KC = K >> 6;
    int NCH = 3 * KC;

    const bf16* Ahb = Ah + (size_t)m0 * K;
    const bf16* Alb = Al + (size_t)m0 * K;
    const bf16* Bhb = Bh + (size_t)n0 * K;
    const bf16* Blb = Bl + (size_t)n0 * K;

    int lrow[4], lch[4];
    #pragma unroll
    for (int i = 0; i < 4; i++) {
        int idx = tid + i * 256;
        lrow[i] = idx >> 3; lch[i] = idx & 7;
    }

    uint32_t aBase = sb + (uint32_t)((wm * 64 + ((l >> 3) & 1) * 8 + (l & 7)) * ROWB + (l >> 4) * 16);
    uint32_t bBase = sb + TILEB + (uint32_t)((wn * 32 + (l >> 4) * 8 + (l & 7)) * ROWB + ((l >> 3) & 1) * 16);

    float acc[4][4][4];
    #pragma unroll
    for (int i = 0; i < 4; i++)
        #pragma unroll
        for (int j = 0; j < 4; j++)
            #pragma unroll
            for (int q = 0; q < 4; q++) acc[i][j][q] = 0.f;

    // prologue: chunks 0,1 (both in segment 0 since KC >= 16)
    #pragma unroll
    for (int s = 0; s < 2; s++) {
        size_t kc = (size_t)s * 64;
        #pragma unroll
        for (int i = 0; i < 4; i++) {
            uint32_t so = (uint32_t)(s * STAGEB + lrow[i] * ROWB + lch[i] * 16);
            cp16(sb + so,         Ahb + (size_t)lrow[i] * K + kc + lch[i] * 8);
            cp16(sb + TILEB + so, Bhb + (size_t)lrow[i] * K + kc + lch[i] * 8);
        }
        asm volatile("cp.async.commit_group;" ::: "memory");
    }

    for (int c = 0; c < NCH; c++) {
        asm volatile("cp.async.wait_group 1;" ::: "memory");
        __syncthreads();
        int nc = c + 2;
        if (nc < NCH) {
            int buf = nc % 3;
            int seg = (nc >= KC) + (nc >= 2 * KC);
            int kk = nc - seg * KC;
            const bf16* Asrc = (seg == 2) ? Alb : Ahb;
            const bf16* Bsrc = (seg == 1) ? Blb : Bhb;
            size_t kc = (size_t)kk * 64;
            #pragma unroll
            for (int i = 0; i < 4; i++) {
                uint32_t so = (uint32_t)(buf * STAGEB + lrow[i] * ROWB + lch[i] * 16);
                cp16(sb + so,         Asrc + (size_t)lrow[i] * K + kc + lch[i] * 8);
                cp16(sb + TILEB + so, Bsrc + (size_t)lrow[i] * K + kc + lch[i] * 8);
            }
        }
        asm volatile("cp.async.commit_group;" ::: "memory");

        uint32_t as0 = aBase + (uint32_t)((c % 3) * STAGEB);
        uint32_t bs0 = bBase + (uint32_t)((c % 3) * STAGEB);
        #pragma unroll
        for (int ks = 0; ks < 4; ks++) {
            uint32_t ar[4][4], br[2][4];
            #pragma unroll
            for (int mt = 0; mt < 4; mt++)
                ldsm_x4(ar[mt], as0 + mt * (16 * ROWB) + ks * 32);
            #pragma unroll
            for (int p = 0; p < 2; p++)
                ldsm_x4(br[p], bs0 + p * (16 * ROWB) + ks * 32);
            #pragma unroll
            for (int mt = 0; mt < 4; mt++) {
                #pragma unroll
                for (int nt = 0; nt < 4; nt++) {
                    int p = nt >> 1, hh = (nt & 1) * 2;
                    mma16816(acc[mt][nt], ar[mt], br[p][hh], br[p][hh + 1]);
                }
            }
        }
    }

    // epilogue
    int g = l >> 2, t4 = l & 3;
    #pragma unroll
    for (int mt = 0; mt < 4; mt++) {
        int row0 = m0 + wm * 64 + mt * 16 + g;
        #pragma unroll
        for (int nt = 0; nt < 4; nt++) {
            int col = n0 + wn * 32 + nt * 8 + t4 * 2;
            float2 bv = *(const float2*)(bias + col);
            float v0 = acc[mt][nt][0] + bv.x;
            float v1 = acc[mt][nt][1] + bv.y;
            float v2 = acc[mt][nt][2] + bv.x;
            float v3 = acc[mt][nt][3] + bv.y;
            if (RELU) {
                v0 = fmaxf(v0, 0.f); v1 = fmaxf(v1, 0.f);
                v2 = fmaxf(v2, 0.f); v3 = fmaxf(v3, 0.f);
            }
            if (WSPLIT) {
                bf16 h0,l0,h1,l1;
                split2(v0,h0,l0); split2(v1,h1,l1);
                *(uint32_t*)(C3h + (size_t)row0 * N + col) = pk2(h0,h1);
                *(uint32_t*)(C3l + (size_t)row0 * N + col) = pk2(l0,l1);
                split2(v2,h0,l0); split2(v3,h1,l1);
                *(uint32_t*)(C3h + (size_t)(row0 + 8) * N + col) = pk2(h0,h1);
                *(uint32_t*)(C3l + (size_t)(row0 + 8) * N + col) = pk2(l0,l1);
            } else {
                if (HASRES) {
                    float2 r1 = *(const float2*)(res + (size_t)row0 * N + col);
                    float2 r2 = *(const float2*)(res + (size_t)(row0 + 8) * N + col);
                    v0 += r1.x; v1 += r1.y; v2 += r2.x; v3 += r2.y;
                }
                *(float2*)(C + (size_t)row0 * N + col)       = make_float2(v0, v1);
                *(float2*)(C + (size_t)(row0 + 8) * N + col) = make_float2(v2, v3);
            }
        }
    }
}

// ------------------------------------------------------------------
// HMMA flash attention (causal), triple-split bf16, registers-direct P,
// Q fragments hoisted to registers (loop-invariant).
// 1-D grid, GLOBAL heavy-first ordering: qi = 15 - bid/32, bh = bid%32.
// ------------------------------------------------------------------
#define LDROW 400
#define VROW  272
#define AQ_OFF   0u
#define AK_OFF   51200u
#define AV_OFF   102400u
#define ASMEM    137216

__global__ __launch_bounds__(256) void attn_hmma(
    const bf16* __restrict__ q3, const bf16* __restrict__ k3,
    const bf16* __restrict__ v3, const float* __restrict__ x,
    float* __restrict__ x1)
{
    extern __shared__ __align__(128) unsigned char sm[];
    uint32_t sb = smem_u32(sm);
    int tid = threadIdx.x, w = tid >> 5, l = tid & 31;
    int g = l >> 2, t4 = l & 3;
    int bid = blockIdx.x;
    int bh = bid & 31;
    int qi = (TLEN / 128 - 1) - (bid >> 5);   // heavy tiles launch first, globally
    int b = bh >> 4, h = bh & 15;
    int q0 = qi * 128;
    int ktn = 2 * qi + 2;

    const bf16* qb = q3 + ((size_t)bh * TLEN + q0) * 192;
    const bf16* kb = k3 + (size_t)bh * TLEN * 192;
    const bf16* vb = v3 + (size_t)bh * 64 * 4096;

    // Q tile: 128 rows x 24 chunks
    for (int i = tid; i < 3072; i += 256) {
        int r = i / 24, c = i % 24;
        cp16(sb + AQ_OFF + r * LDROW + c * 16, qb + (size_t)r * 192 + c * 8);
    }
    asm volatile("cp.async.commit_group;" ::: "memory");
    // KV tile 0 into buf 0
    for (int i = tid; i < 1536; i += 256) {
        int r = i / 24, c = i % 24;
        cp16(sb + AK_OFF + r * LDROW + c * 16, kb + (size_t)r * 192 + c * 8);
    }
    for (int i = tid; i < 1024; i += 256) {
        int r = i >> 4, c = i & 15;
        cp16(sb + AV_OFF + r * VROW + c * 16, vb + (size_t)r * 4096 + c * 8);
    }
    asm volatile("cp.async.commit_group;" ::: "memory");

    uint32_t rowPartA = (uint32_t)((16 * w + ((l >> 3) & 1) * 8 + (l & 7)) * LDROW + (l >> 4) * 16);
    uint32_t aQ = sb + AQ_OFF + rowPartA;
    uint32_t bPartK = (uint32_t)(((l >> 4) * 8 + (l & 7)) * LDROW + ((l >> 3) & 1) * 16);
    uint32_t bPartV = (uint32_t)(((l >> 4) * 8 + (l & 7)) * VROW + ((l >> 3) & 1) * 16);

    float m_[2] = {-1e30f, -1e30f};
    float l_[2] = {0.f, 0.f};
    float oacc[8][4];
    #pragma unroll
    for (int nt = 0; nt < 8; nt++)
        #pragma unroll
        for (int q = 0; q < 4; q++) oacc[nt][q] = 0.f;

    uint32_t qr[12][4];   // Q fragments, loaded once (loop-invariant)

    for (int kt = 0; kt < ktn; kt++) {
        asm volatile("cp.async.wait_group 0;" ::: "memory");
        __syncthreads();
        if (kt == 0) {
            #pragma unroll
            for (int ks = 0; ks < 12; ks++)
                ldsm_x4(qr[ks], aQ + ks * 32);
        }
        if (kt + 1 < ktn) {
            uint32_t kboff = ((kt + 1) & 1) * 25600u;
            uint32_t vboff = ((kt + 1) & 1) * 17408u;
            for (int i = tid; i < 1536; i += 256) {
                int r = i / 24, c = i % 24;
                cp16(sb + AK_OFF + kboff + r * LDROW + c * 16,
                     kb + ((size_t)(kt + 1) * 64 + r) * 192 + c * 8);
            }
            for (int i = tid; i < 1024; i += 256) {
                int r = i >> 4, c = i & 15;
                cp16(sb + AV_OFF + vboff + r * VROW + c * 16,
                     vb + (size_t)r * 4096 + (size_t)(kt + 1) * 128 + c * 8);
            }
        }
        asm volatile("cp.async.commit_group;" ::: "memory");

        uint32_t bK = sb + AK_OFF + (kt & 1) * 25600u + bPartK;
        uint32_t bV = sb + AV_OFF + (kt & 1) * 17408u + bPartV;

        // S = Q K^T
        float sacc[8][4];
        #pragma unroll
        for (int nt = 0; nt < 8; nt++)
            #pragma unroll
            for (int q = 0; q < 4; q++) sacc[nt][q] = 0.f;
        #pragma unroll
        for (int ks = 0; ks < 12; ks++) {
            uint32_t br[4][4];
            #pragma unroll
            for (int p = 0; p < 4; p++)
                ldsm_x4(br[p], bK + p * (16 * LDROW) + ks * 32);
            #pragma unroll
            for (int nt = 0; nt < 8; nt++)
                mma16816(sacc[nt], qr[ks], br[nt >> 1][(nt & 1) * 2], br[nt >> 1][(nt & 1) * 2 + 1]);
        }

        int k0 = kt * 64;
        if (k0 + 63 > q0) {
            int r0 = q0 + 16 * w + g, r1 = r0 + 8;
            #pragma unroll
            for (int nt = 0; nt < 8; nt++) {
                int c0 = k0 + nt * 8 + t4 * 2;
                sacc[nt][0] = (c0     > r0) ? -1e30f : sacc[nt][0] * 0.125f;
                sacc[nt][1] = (c0 + 1 > r0) ? -1e30f : sacc[nt][1] * 0.125f;
                sacc[nt][2] = (c0     > r1) ? -1e30f : sacc[nt][2] * 0.125f;
                sacc[nt][3] = (c0 + 1 > r1) ? -1e30f : sacc[nt][3] * 0.125f;
            }
        } else {
            #pragma unroll
            for (int nt = 0; nt < 8; nt++)
                #pragma unroll
                for (int q = 0; q < 4; q++) sacc[nt][q] *= 0.125f;
        }

        // online softmax per row-half
        #pragma unroll
        for (int h2 = 0; h2 < 2; h2++) {
            float mx = -1e30f;
            #pragma unroll
            for (int nt = 0; nt < 8; nt++)
                mx = fmaxf(mx, fmaxf(sacc[nt][h2 * 2], sacc[nt][h2 * 2 + 1]));
            mx = fmaxf(mx, __shfl_xor_sync(0xffffffffu, mx, 1));
            mx = fmaxf(mx, __shfl_xor_sync(0xffffffffu, mx, 2));
            float mn = fmaxf(m_[h2], mx);
            float al = __expf(m_[h2] - mn);
            float sum = 0.f;
            #pragma unroll
            for (int nt = 0; nt < 8; nt++) {
                float p0 = __expf(sacc[nt][h2 * 2]     - mn);
                float p1 = __expf(sacc[nt][h2 * 2 + 1] - mn);
                sacc[nt][h2 * 2] = p0; sacc[nt][h2 * 2 + 1] = p1;
                sum += p0 + p1;
            }
            sum += __shfl_xor_sync(0xffffffffu, sum, 1);
            sum += __shfl_xor_sync(0xffffffffu, sum, 2);
            l_[h2] = l_[h2] * al + sum;
            m_[h2] = mn;
            #pragma unroll
            for (int nt = 0; nt < 8; nt++) {
                oacc[nt][h2 * 2]     *= al;
                oacc[nt][h2 * 2 + 1] *= al;
            }
        }

        // O += P V  — P direct from registers (C-frag == A-frag layout)
        #pragma unroll
        for (int kbk = 0; kbk < 4; kbk++) {
            uint32_t aH[4], aL[4];
            aH[0] = pk2(hi_bf(sacc[2*kbk][0]),   hi_bf(sacc[2*kbk][1]));
            aH[1] = pk2(hi_bf(sacc[2*kbk][2]),   hi_bf(sacc[2*kbk][3]));
            aH[2] = pk2(hi_bf(sacc[2*kbk+1][0]), hi_bf(sacc[2*kbk+1][1]));
            aH[3] = pk2(hi_bf(sacc[2*kbk+1][2]), hi_bf(sacc[2*kbk+1][3]));
            aL[0] = pk2(lo_bf(sacc[2*kbk][0]),   lo_bf(sacc[2*kbk][1]));
            aL[1] = pk2(lo_bf(sacc[2*kbk][2]),   lo_bf(sacc[2*kbk][3]));
            aL[2] = pk2(lo_bf(sacc[2*kbk+1][0]), lo_bf(sacc[2*kbk+1][1]));
            aL[3] = pk2(lo_bf(sacc[2*kbk+1][2]), lo_bf(sacc[2*kbk+1][3]));

            uint32_t vh[4][4], vl[4][4];
            #pragma unroll
            for (int p = 0; p < 4; p++) {
                ldsm_x4(vh[p], bV + p * (16 * VROW) + kbk * 32);
                ldsm_x4(vl[p], bV + 128 + p * (16 * VROW) + kbk * 32);
            }
            #pragma unroll
            for (int nt = 0; nt < 8; nt++) {
                int p = nt >> 1, hh = (nt & 1) * 2;
                mma16816(oacc[nt], aH, vh[p][hh], vh[p][hh + 1]);
                mma16816(oacc[nt], aH, vl[p][hh], vl[p][hh + 1]);
                mma16816(oacc[nt], aL, vh[p][hh], vh[p][hh + 1]);
            }
        }
    }

    // epilogue: y/l + residual x -> x1
    #pragma unroll
    for (int h2 = 0; h2 < 2; h2++) {
        float inv = 1.f / l_[h2];
        int row = b * TLEN + q0 + 16 * w + g + 8 * h2;
        const float* xr = x  + (size_t)row * EMB + h * 64;
        float*       xo = x1 + (size_t)row * EMB + h * 64;
        #pragma unroll
        for (int nt = 0; nt < 8; nt++) {
            int c = nt * 8 + t4 * 2;
            float2 xv = *(const float2*)(xr + c);
            float2 yv;
            yv.x = oacc[nt][h2 * 2]     * inv + xv.x;
            yv.y = oacc[nt][h2 * 2 + 1] * inv + xv.y;
            *(float2*)(xo + c) = yv;
        }
    }
}

// ------------------------------------------------------------------
extern "C" void kernel_launch(void* const* d_in, const int* in_sizes, int n_in,
                              void* d_out, int out_size)
{
    const float* x      = (const float*)d_in[0];
    const float* ln1s   = (const float*)d_in[1];
    const float* ln1b   = (const float*)d_in[2];
    const float* w_qkv  = (const float*)d_in[3];
    const float* b_qkv  = (const float*)d_in[4];
    const float* ln2s   = (const float*)d_in[5];
    const float* ln2b   = (const float*)d_in[6];
    const float* w_fc   = (const float*)d_in[7];
    const float* b_fc   = (const float*)d_in[8];
    const float* w_proj = (const float*)d_in[9];
    const float* b_proj = (const float*)d_in[10];
    float* out = (float*)d_out;

    float *qkv, *x1;
    bf16 *lnh, *lnl, *wh, *wl, *a3h, *a3l, *q3, *k3, *v3;
    cudaGetSymbolAddress((void**)&qkv, g_qkv);
    cudaGetSymbolAddress((void**)&x1,  g_x1);
    cudaGetSymbolAddress((void**)&lnh, g_lnh);
    cudaGetSymbolAddress((void**)&lnl, g_lnl);
    cudaGetSymbolAddress((void**)&wh,  g_wh);
    cudaGetSymbolAddress((void**)&wl,  g_wl);
    cudaGetSymbolAddress((void**)&a3h, g_a3h);
    cudaGetSymbolAddress((void**)&a3l, g_a3l);
    cudaGetSymbolAddress((void**)&q3,  g_q3);
    cudaGetSymbolAddress((void**)&k3,  g_k3);
    cudaGetSymbolAddress((void**)&v3,  g_v3);

    cudaFuncSetAttribute(attn_hmma, cudaFuncAttributeMaxDynamicSharedMemorySize, ASMEM);
    cudaFuncSetAttribute(gemm_tc<false,false,false>, cudaFuncAttributeMaxDynamicSharedMemorySize, GSMEM);
    cudaFuncSetAttribute(gemm_tc<true,false,true>,   cudaFuncAttributeMaxDynamicSharedMemorySize, GSMEM);
    cudaFuncSetAttribute(gemm_tc<false,true,false>,  cudaFuncAttributeMaxDynamicSharedMemorySize, GSMEM);

    // 1. lnh/lnl = split(LN1(x))
    ln_split<<<MROWS, 256>>>(x, ln1s, ln1b, lnh, lnl);
    // 2. qkv = ln1 @ w_qkv + b_qkv
    convert_wt<<<dim3(EMB / 32, 3 * EMB / 32), dim3(32, 32)>>>(w_qkv, wh, wl, EMB, 3 * EMB);
    gemm_tc<false,false,false><<<dim3(3 * EMB / 128, MROWS / 128), 256, GSMEM>>>(
        lnh, lnl, wh, wl, b_qkv, nullptr, qkv, nullptr, nullptr, 3 * EMB, EMB);
    // 3. split/transpose q,k,v
    prep_attn<<<dim3(TLEN / 64, 32), 256>>>(qkv, q3, k3, v3);
    // 4. x1 = x + attention  (fused residual, global heavy-first order)
    attn_hmma<<<(TLEN / 128) * 32, 256, ASMEM>>>(q3, k3, v3, x, x1);
    // 5. lnh/lnl = split(LN2(x1))
    ln_split<<<MROWS, 256>>>(x1, ln2s, ln2b, lnh, lnl);
    // 6. a3h/a3l = split(relu(ln2 @ w_fc + b_fc))
    convert_wt<<<dim3(EMB / 32, HID / 32), dim3(32, 32)>>>(w_fc, wh, wl, EMB, HID);
    gemm_tc<true,false,true><<<dim3(HID / 128, MROWS / 128), 256, GSMEM>>>(
        lnh, lnl, wh, wl, b_fc, nullptr, nullptr, a3h, a3l, HID, EMB);
    // 7. out = x1 + fc @ w_proj + b_proj
    convert_wt<<<dim3(HID / 32, EMB / 32), dim3(32, 32)>>>(w_proj, wh, wl, HID, EMB);
    gemm_tc<false,true,false><<<dim3(EMB / 128, MROWS / 128), 256, GSMEM>>>(
        a3h, a3l, wh, wl, b_proj, x1, out, nullptr, nullptr, EMB, HID);
}

// round 15
// speedup vs baseline: 1.5552x; 1.0148x over previous
#include <cuda_runtime.h>
#include <cuda_bf16.h>
#include <math.h>
#include <stdint.h>

#define BATCH 2
#define TLEN  2048
#define EMB   1024
#define NHEAD 16
#define HDIM  64
#define MROWS (BATCH*TLEN)   /* 4096 */
#define HID   (4*EMB)        /* 4096 */

typedef __nv_bfloat16 bf16;

// ---- scratch (device globals; no allocation allowed) ----
__device__ float g_qkv[(size_t)MROWS * 3 * EMB];          // only V region used now
__device__ float g_x1 [(size_t)MROWS * EMB];
__device__ bf16  g_lnh[(size_t)MROWS * EMB];              // LN split hi plane
__device__ bf16  g_lnl[(size_t)MROWS * EMB];              // LN split lo plane
__device__ bf16  g_wh [(size_t)4194304];                  // weight hi plane [N,K]
__device__ bf16  g_wl [(size_t)4194304];                  // weight lo plane [N,K]
__device__ bf16  g_a3h[(size_t)MROWS * HID];              // fc out hi plane
__device__ bf16  g_a3l[(size_t)MROWS * HID];              // fc out lo plane
__device__ bf16  g_q3 [(size_t)32 * TLEN * 192];          // Q split [bh,t,192]
__device__ bf16  g_k3 [(size_t)32 * TLEN * 192];          // K split [bh,t,192]
__device__ bf16  g_v3 [(size_t)32 * HDIM * 4096];         // V planes [bh,dv, tile:64vh|64vl]

__device__ __forceinline__ uint32_t smem_u32(const void* p) {
    uint32_t a;
    asm("{ .reg .u64 t; cvta.to.shared.u64 t, %1; cvt.u32.u64 %0, t; }" : "=r"(a) : "l"(p));
    return a;
}
__device__ __forceinline__ void cp16(uint32_t saddr, const void* gaddr) {
    asm volatile("cp.async.cg.shared.global [%0], [%1], 16;" :: "r"(saddr), "l"(gaddr) : "memory");
}
__device__ __forceinline__ void ldsm_x4(uint32_t* r, uint32_t addr) {
    asm volatile("ldmatrix.sync.aligned.m8n8.x4.shared.b16 {%0,%1,%2,%3}, [%4];"
                 : "=r"(r[0]), "=r"(r[1]), "=r"(r[2]), "=r"(r[3]) : "r"(addr));
}
__device__ __forceinline__ void mma16816(float* c, const uint32_t* a, uint32_t b0, uint32_t b1) {
    asm volatile(
        "mma.sync.aligned.m16n8k16.row.col.f32.bf16.bf16.f32 "
        "{%0,%1,%2,%3}, {%4,%5,%6,%7}, {%8,%9}, {%0,%1,%2,%3};"
        : "+f"(c[0]), "+f"(c[1]), "+f"(c[2]), "+f"(c[3])
        : "r"(a[0]), "r"(a[1]), "r"(a[2]), "r"(a[3]), "r"(b0), "r"(b1));
}
__device__ __forceinline__ uint32_t pk2(bf16 a, bf16 b) {
    return (uint32_t)__bfloat16_as_ushort(a) | ((uint32_t)__bfloat16_as_ushort(b) << 16);
}
__device__ __forceinline__ void split2(float v, bf16& hi, bf16& lo) {
    hi = __float2bfloat16(v);
    lo = __float2bfloat16(v - __bfloat162float(hi));
}
__device__ __forceinline__ bf16 hi_bf(float v) { return __float2bfloat16(v); }
__device__ __forceinline__ bf16 lo_bf(float v) {
    bf16 h = __float2bfloat16(v);
    return __float2bfloat16(v - __bfloat162float(h));
}

// ------------------------------------------------------------------
// Weight conversion: W[K,N] f32 -> hi/lo planes [N,K] (transposed)
// ------------------------------------------------------------------
__global__ __launch_bounds__(1024) void convert_wt(
    const float* __restrict__ W, bf16* __restrict__ wh, bf16* __restrict__ wl,
    int K, int N)
{
    __shared__ float t[32][33];
    int tx = threadIdx.x, ty = threadIdx.y;
    int k0 = blockIdx.x * 32, n0 = blockIdx.y * 32;
    t[ty][tx] = W[(size_t)(k0 + ty) * N + n0 + tx];
    __syncthreads();
    float w = t[tx][ty];               // k = k0+tx, n = n0+ty
    bf16 hi, lo; split2(w, hi, lo);
    size_t o = (size_t)(n0 + ty) * K + (k0 + tx);
    wh[o] = hi; wl[o] = lo;
}

// ------------------------------------------------------------------
// LayerNorm fused with activation split -> hi/lo planes [M,K]
// ------------------------------------------------------------------
__global__ __launch_bounds__(256) void ln_split(
    const float* __restrict__ x, const float* __restrict__ scale,
    const float* __restrict__ shift, bf16* __restrict__ lnh, bf16* __restrict__ lnl)
{
    int row = blockIdx.x;
    int t = threadIdx.x;
    const float4* xr = (const float4*)(x + (size_t)row * EMB);
    float4 v = xr[t];
    float s  = v.x + v.y + v.z + v.w;
    float sq = v.x*v.x + v.y*v.y + v.z*v.z + v.w*v.w;

    __shared__ float red[16];
    __shared__ float mv[2];
    #pragma unroll
    for (int o = 16; o > 0; o >>= 1) {
        s  += __shfl_xor_sync(0xffffffffu, s,  o);
        sq += __shfl_xor_sync(0xffffffffu, sq, o);
    }
    if ((t & 31) == 0) { red[t >> 5] = s; red[8 + (t >> 5)] = sq; }
    __syncthreads();
    if (t == 0) {
        float S = 0.f, SQ = 0.f;
        #pragma unroll
        for (int i = 0; i < 8; i++) { S += red[i]; SQ += red[8 + i]; }
        float mean = S * (1.0f / EMB);
        float var  = SQ * (1.0f / EMB) - mean * mean;
        mv[0] = mean; mv[1] = rsqrtf(var + 1e-5f);
    }
    __syncthreads();
    float mean = mv[0], inv = mv[1];
    float4 sc = ((const float4*)scale)[t];
    float4 sh = ((const float4*)shift)[t];
    float o0 = (v.x - mean) * inv * sc.x + sh.x;
    float o1 = (v.y - mean) * inv * sc.y + sh.y;
    float o2 = (v.z - mean) * inv * sc.z + sh.z;
    float o3 = (v.w - mean) * inv * sc.w + sh.w;
    bf16 h0,l0,h1,l1,h2,l2,h3,l3;
    split2(o0,h0,l0); split2(o1,h1,l1); split2(o2,h2,l2); split2(o3,h3,l3);
    uint32_t* ph = (uint32_t*)(lnh + (size_t)row * EMB) + 2 * t;
    ph[0] = pk2(h0,h1); ph[1] = pk2(h2,h3);
    uint32_t* pl = (uint32_t*)(lnl + (size_t)row * EMB) + 2 * t;
    pl[0] = pk2(l0,l1); pl[1] = pk2(l2,l3);
}

// ------------------------------------------------------------------
// prep_v: V only — transpose + hi/lo plane split (Q/K now fused in GEMM)
// ------------------------------------------------------------------
__global__ __launch_bounds__(256) void prep_v(
    const float* __restrict__ qkv, bf16* __restrict__ v3)
{
    __shared__ float vt[64][65];
    int bh = blockIdx.y;
    int tt = blockIdx.x;
    int b = bh >> 4, h = bh & 15;
    int t0 = tt * 64;
    int tid = threadIdx.x;
    int r = tid >> 2, cc = (tid & 3) * 16;
    const float* base = qkv + ((size_t)(b * TLEN + t0 + r)) * 3072 + 2048 + h * 64;

    float vv[16];
    #pragma unroll
    for (int j = 0; j < 4; j++)
        *(float4*)(vv + 4 * j) = *(const float4*)(base + cc + 4 * j);

    #pragma unroll
    for (int j = 0; j < 16; j++) vt[cc + j][r] = vv[j];
    __syncthreads();
    {
        uint32_t oh[8], ol[8];
        #pragma unroll
        for (int j = 0; j < 16; j += 2) {
            bf16 a0,b0,a1,b1;
            split2(vt[r][cc + j], a0, b0); split2(vt[r][cc + j + 1], a1, b1);
            oh[j >> 1] = pk2(a0, a1);
            ol[j >> 1] = pk2(b0, b1);
        }
        bf16* vrow = v3 + ((size_t)bh * 64 + r) * 4096 + (size_t)tt * 128;
        uint4* dh = (uint4*)(vrow + cc);
        dh[0] = ((uint4*)oh)[0]; dh[1] = ((uint4*)oh)[1];
        uint4* dl = (uint4*)(vrow + 64 + cc);
        dl[0] = ((uint4*)ol)[0]; dl[1] = ((uint4*)ol)[1];
    }
}

// ------------------------------------------------------------------
// HMMA GEMM, plane-segmented triple split:
//   C = Ah.Bh^T + Ah.Bl^T + Al.Bh^T  (+bias, +relu, +res | split-out | qk-pack)
// BM=128 BN=128 BK=64, 3-stage cp.async, 8 warps (2x4), warp 64x32, occ 2.
// QKPACK: Q-region tiles (n0<1024) write A-pattern to q3 (C3h);
//         K-region tiles write B-pattern to k3 (C3l); V region plain fp32 C.
// ------------------------------------------------------------------
#define ROWB   144
#define TILEB  (128*ROWB)      /* 18432 */
#define STAGEB (2*TILEB)       /* 36864 */
#define GSMEM  (3*STAGEB)      /* 110592 */

template<bool RELU, bool HASRES, bool WSPLIT, bool QKPACK>
__global__ __launch_bounds__(256, 2)
void gemm_tc(const bf16* __restrict__ Ah, const bf16* __restrict__ Al,
             const bf16* __restrict__ Bh, const bf16* __restrict__ Bl,
             const float* __restrict__ bias, const float* __restrict__ res,
             float* __restrict__ C, bf16* __restrict__ C3h, bf16* __restrict__ C3l,
             int N, int K)
{
    extern __shared__ __align__(128) unsigned char smem[];
    uint32_t sb = smem_u32(smem);
    int tid = threadIdx.x, w = tid >> 5, l = tid & 31;
    int wm = w >> 2, wn = w & 3;
    int m0 = blockIdx.y * 128, n0 = blockIdx.x * 128;
    int KC = K >> 6;
    int NCH = 3 * KC;

    const bf16* Ahb = Ah + (size_t)m0 * K;
    const bf16* Alb = Al + (size_t)m0 * K;
    const bf16* Bhb = Bh + (size_t)n0 * K;
    const bf16* Blb = Bl + (size_t)n0 * K;

    int lrow[4], lch[4];
    #pragma unroll
    for (int i = 0; i < 4; i++) {
        int idx = tid + i * 256;
        lrow[i] = idx >> 3; lch[i] = idx & 7;
    }

    uint32_t aBase = sb + (uint32_t)((wm * 64 + ((l >> 3) & 1) * 8 + (l & 7)) * ROWB + (l >> 4) * 16);
    uint32_t bBase = sb + TILEB + (uint32_t)((wn * 32 + (l >> 4) * 8 + (l & 7)) * ROWB + ((l >> 3) & 1) * 16);

    float acc[4][4][4];
    #pragma unroll
    for (int i = 0; i < 4; i++)
        #pragma unroll
        for (int j = 0; j < 4; j++)
            #pragma unroll
            for (int q = 0; q < 4; q++) acc[i][j][q] = 0.f;

    // prologue: chunks 0,1 (both in segment 0 since KC >= 16)
    #pragma unroll
    for (int s = 0; s < 2; s++) {
        size_t kc = (size_t)s * 64;
        #pragma unroll
        for (int i = 0; i < 4; i++) {
            uint32_t so = (uint32_t)(s * STAGEB + lrow[i] * ROWB + lch[i] * 16);
            cp16(sb + so,         Ahb + (size_t)lrow[i] * K + kc + lch[i] * 8);
            cp16(sb + TILEB + so, Bhb + (size_t)lrow[i] * K + kc + lch[i] * 8);
        }
        asm volatile("cp.async.commit_group;" ::: "memory");
    }

    for (int c = 0; c < NCH; c++) {
        asm volatile("cp.async.wait_group 1;" ::: "memory");
        __syncthreads();
        int nc = c + 2;
        if (nc < NCH) {
            int buf = nc % 3;
            int seg = (nc >= KC) + (nc >= 2 * KC);
            int kk = nc - seg * KC;
            const bf16* Asrc = (seg == 2) ? Alb : Ahb;
            const bf16* Bsrc = (seg == 1) ? Blb : Bhb;
            size_t kc = (size_t)kk * 64;
            #pragma unroll
            for (int i = 0; i < 4; i++) {
                uint32_t so = (uint32_t)(buf * STAGEB + lrow[i] * ROWB + lch[i] * 16);
                cp16(sb + so,         Asrc + (size_t)lrow[i] * K + kc + lch[i] * 8);
                cp16(sb + TILEB + so, Bsrc + (size_t)lrow[i] * K + kc + lch[i] * 8);
            }
        }
        asm volatile("cp.async.commit_group;" ::: "memory");

        uint32_t as0 = aBase + (uint32_t)((c % 3) * STAGEB);
        uint32_t bs0 = bBase + (uint32_t)((c % 3) * STAGEB);
        #pragma unroll
        for (int ks = 0; ks < 4; ks++) {
            uint32_t ar[4][4], br[2][4];
            #pragma unroll
            for (int mt = 0; mt < 4; mt++)
                ldsm_x4(ar[mt], as0 + mt * (16 * ROWB) + ks * 32);
            #pragma unroll
            for (int p = 0; p < 2; p++)
                ldsm_x4(br[p], bs0 + p * (16 * ROWB) + ks * 32);
            #pragma unroll
            for (int mt = 0; mt < 4; mt++) {
                #pragma unroll
                for (int nt = 0; nt < 4; nt++) {
                    int p = nt >> 1, hh = (nt & 1) * 2;
                    mma16816(acc[mt][nt], ar[mt], br[p][hh], br[p][hh + 1]);
                }
            }
        }
    }

    // epilogue
    int g = l >> 2, t4 = l & 3;
    int region = n0 >> 10;   // 0=Q, 1=K, 2=V (regions are 1024-aligned; BN=128 stays inside)
    #pragma unroll
    for (int mt = 0; mt < 4; mt++) {
        int row0 = m0 + wm * 64 + mt * 16 + g;
        #pragma unroll
        for (int nt = 0; nt < 4; nt++) {
            int col = n0 + wn * 32 + nt * 8 + t4 * 2;
            float2 bv = *(const float2*)(bias + col);
            float v0 = acc[mt][nt][0] + bv.x;
            float v1 = acc[mt][nt][1] + bv.y;
            float v2 = acc[mt][nt][2] + bv.x;
            float v3 = acc[mt][nt][3] + bv.y;
            if (RELU) {
                v0 = fmaxf(v0, 0.f); v1 = fmaxf(v1, 0.f);
                v2 = fmaxf(v2, 0.f); v3 = fmaxf(v3, 0.f);
            }
            if (QKPACK && region < 2) {
                // pack split patterns straight into q3 / k3
                int hcol = (col >> 6) & 15;
                int dd = col & 63;
                int bb = row0 >> 11, tt0 = row0 & 2047;
                bf16* dst = (region == 0) ? C3h : C3l;   // q3 : k3
                size_t base = ((size_t)(bb * 16 + hcol) * TLEN + tt0) * 192 + 3 * dd;
                bf16 a0,b0,a1,b1;
                split2(v0,a0,b0); split2(v1,a1,b1);
                uint32_t* p = (uint32_t*)(dst + base);
                if (region == 0) { p[0] = pk2(a0,a0); p[1] = pk2(b0,a1); p[2] = pk2(a1,b1); }
                else             { p[0] = pk2(a0,b0); p[1] = pk2(a0,a1); p[2] = pk2(b1,a1); }
                split2(v2,a0,b0); split2(v3,a1,b1);
                uint32_t* q = (uint32_t*)(dst + base + 8 * 192);
                if (region == 0) { q[0] = pk2(a0,a0); q[1] = pk2(b0,a1); q[2] = pk2(a1,b1); }
                else             { q[0] = pk2(a0,b0); q[1] = pk2(a0,a1); q[2] = pk2(b1,a1); }
            } else if (WSPLIT) {
                bf16 h0,l0,h1,l1;
                split2(v0,h0,l0); split2(v1,h1,l1);
                *(uint32_t*)(C3h + (size_t)row0 * N + col) = pk2(h0,h1);
                *(uint32_t*)(C3l + (size_t)row0 * N + col) = pk2(l0,l1);
                split2(v2,h0,l0); split2(v3,h1,l1);
                *(uint32_t*)(C3h + (size_t)(row0 + 8) * N + col) = pk2(h0,h1);
                *(uint32_t*)(C3l + (size_t)(row0 + 8) * N + col) = pk2(l0,l1);
            } else {
                if (HASRES) {
                    float2 r1 = *(const float2*)(res + (size_t)row0 * N + col);
                    float2 r2 = *(const float2*)(res + (size_t)(row0 + 8) * N + col);
                    v0 += r1.x; v1 += r1.y; v2 += r2.x; v3 += r2.y;
                }
                *(float2*)(C + (size_t)row0 * N + col)       = make_float2(v0, v1);
                *(float2*)(C + (size_t)(row0 + 8) * N + col) = make_float2(v2, v3);
            }
        }
    }
}

// ------------------------------------------------------------------
// HMMA flash attention (causal), triple-split bf16, registers-direct P,
// Q fragments hoisted to registers (loop-invariant).
// 1-D grid, GLOBAL heavy-first ordering: qi = 15 - bid/32, bh = bid%32.
// ------------------------------------------------------------------
#define LDROW 400
#define VROW  272
#define AQ_OFF   0u
#define AK_OFF   51200u
#define AV_OFF   102400u
#define ASMEM    137216

__global__ __launch_bounds__(256) void attn_hmma(
    const bf16* __restrict__ q3, const bf16* __restrict__ k3,
    const bf16* __restrict__ v3, const float* __restrict__ x,
    float* __restrict__ x1)
{
    extern __shared__ __align__(128) unsigned char sm[];
    uint32_t sb = smem_u32(sm);
    int tid = threadIdx.x, w = tid >> 5, l = tid & 31;
    int g = l >> 2, t4 = l & 3;
    int bid = blockIdx.x;
    int bh = bid & 31;
    int qi = (TLEN / 128 - 1) - (bid >> 5);   // heavy tiles launch first, globally
    int b = bh >> 4, h = bh & 15;
    int q0 = qi * 128;
    int ktn = 2 * qi + 2;

    const bf16* qb = q3 + ((size_t)bh * TLEN + q0) * 192;
    const bf16* kb = k3 + (size_t)bh * TLEN * 192;
    const bf16* vb = v3 + (size_t)bh * 64 * 4096;

    // Q tile: 128 rows x 24 chunks
    for (int i = tid; i < 3072; i += 256) {
        int r = i / 24, c = i % 24;
        cp16(sb + AQ_OFF + r * LDROW + c * 16, qb + (size_t)r * 192 + c * 8);
    }
    asm volatile("cp.async.commit_group;" ::: "memory");
    // KV tile 0 into buf 0
    for (int i = tid; i < 1536; i += 256) {
        int r = i / 24, c = i % 24;
        cp16(sb + AK_OFF + r * LDROW + c * 16, kb + (size_t)r * 192 + c * 8);
    }
    for (int i = tid; i < 1024; i += 256) {
        int r = i >> 4, c = i & 15;
        cp16(sb + AV_OFF + r * VROW + c * 16, vb + (size_t)r * 4096 + c * 8);
    }
    asm volatile("cp.async.commit_group;" ::: "memory");

    uint32_t rowPartA = (uint32_t)((16 * w + ((l >> 3) & 1) * 8 + (l & 7)) * LDROW + (l >> 4) * 16);
    uint32_t aQ = sb + AQ_OFF + rowPartA;
    uint32_t bPartK = (uint32_t)(((l >> 4) * 8 + (l & 7)) * LDROW + ((l >> 3) & 1) * 16);
    uint32_t bPartV = (uint32_t)(((l >> 4) * 8 + (l & 7)) * VROW + ((l >> 3) & 1) * 16);

    float m_[2] = {-1e30f, -1e30f};
    float l_[2] = {0.f, 0.f};
    float oacc[8][4];
    #pragma unroll
    for (int nt = 0; nt < 8; nt++)
        #pragma unroll
        for (int q = 0; q < 4; q++) oacc[nt][q] = 0.f;

    uint32_t qr[12][4];   // Q fragments, loaded once (loop-invariant)

    for (int kt = 0; kt < ktn; kt++) {
        asm volatile("cp.async.wait_group 0;" ::: "memory");
        __syncthreads();
        if (kt == 0) {
            #pragma unroll
            for (int ks = 0; ks < 12; ks++)
                ldsm_x4(qr[ks], aQ + ks * 32);
        }
        if (kt + 1 < ktn) {
            uint32_t kboff = ((kt + 1) & 1) * 25600u;
            uint32_t vboff = ((kt + 1) & 1) * 17408u;
            for (int i = tid; i < 1536; i += 256) {
                int r = i / 24, c = i % 24;
                cp16(sb + AK_OFF + kboff + r * LDROW + c * 16,
                     kb + ((size_t)(kt + 1) * 64 + r) * 192 + c * 8);
            }
            for (int i = tid; i < 1024; i += 256) {
                int r = i >> 4, c = i & 15;
                cp16(sb + AV_OFF + vboff + r * VROW + c * 16,
                     vb + (size_t)r * 4096 + (size_t)(kt + 1) * 128 + c * 8);
            }
        }
        asm volatile("cp.async.commit_group;" ::: "memory");

        uint32_t bK = sb + AK_OFF + (kt & 1) * 25600u + bPartK;
        uint32_t bV = sb + AV_OFF + (kt & 1) * 17408u + bPartV;

        // S = Q K^T
        float sacc[8][4];
        #pragma unroll
        for (int nt = 0; nt < 8; nt++)
            #pragma unroll
            for (int q = 0; q < 4; q++) sacc[nt][q] = 0.f;
        #pragma unroll
        for (int ks = 0; ks < 12; ks++) {
            uint32_t br[4][4];
            #pragma unroll
            for (int p = 0; p < 4; p++)
                ldsm_x4(br[p], bK + p * (16 * LDROW) + ks * 32);
            #pragma unroll
            for (int nt = 0; nt < 8; nt++)
                mma16816(sacc[nt], qr[ks], br[nt >> 1][(nt & 1) * 2], br[nt >> 1][(nt & 1) * 2 + 1]);
        }

        int k0 = kt * 64;
        if (k0 + 63 > q0) {
            int r0 = q0 + 16 * w + g, r1 = r0 + 8;
            #pragma unroll
            for (int nt = 0; nt < 8; nt++) {
                int c0 = k0 + nt * 8 + t4 * 2;
                sacc[nt][0] = (c0     > r0) ? -1e30f : sacc[nt][0] * 0.125f;
                sacc[nt][1] = (c0 + 1 > r0) ? -1e30f : sacc[nt][1] * 0.125f;
                sacc[nt][2] = (c0     > r1) ? -1e30f : sacc[nt][2] * 0.125f;
                sacc[nt][3] = (c0 + 1 > r1) ? -1e30f : sacc[nt][3] * 0.125f;
            }
        } else {
            #pragma unroll
            for (int nt = 0; nt < 8; nt++)
                #pragma unroll
                for (int q = 0; q < 4; q++) sacc[nt][q] *= 0.125f;
        }

        // online softmax per row-half
        #pragma unroll
        for (int h2 = 0; h2 < 2; h2++) {
            float mx = -1e30f;
            #pragma unroll
            for (int nt = 0; nt < 8; nt++)
                mx = fmaxf(mx, fmaxf(sacc[nt][h2 * 2], sacc[nt][h2 * 2 + 1]));
            mx = fmaxf(mx, __shfl_xor_sync(0xffffffffu, mx, 1));
            mx = fmaxf(mx, __shfl_xor_sync(0xffffffffu, mx, 2));
            float mn = fmaxf(m_[h2], mx);
            float al = __expf(m_[h2] - mn);
            float sum = 0.f;
            #pragma unroll
            for (int nt = 0; nt < 8; nt++) {
                float p0 = __expf(sacc[nt][h2 * 2]     - mn);
                float p1 = __expf(sacc[nt][h2 * 2 + 1] - mn);
                sacc[nt][h2 * 2] = p0; sacc[nt][h2 * 2 + 1] = p1;
                sum += p0 + p1;
            }
            sum += __shfl_xor_sync(0xffffffffu, sum, 1);
            sum += __shfl_xor_sync(0xffffffffu, sum, 2);
            l_[h2] = l_[h2] * al + sum;
            m_[h2] = mn;
            #pragma unroll
            for (int nt = 0; nt < 8; nt++) {
                oacc[nt][h2 * 2]     *= al;
                oacc[nt][h2 * 2 + 1] *= al;
            }
        }

        // O += P V  — P direct from registers (C-frag == A-frag layout)
        #pragma unroll
        for (int kbk = 0; kbk < 4; kbk++) {
            uint32_t aH[4], aL[4];
            aH[0] = pk2(hi_bf(sacc[2*kbk][0]),   hi_bf(sacc[2*kbk][1]));
            aH[1] = pk2(hi_bf(sacc[2*kbk][2]),   hi_bf(sacc[2*kbk][3]));
            aH[2] = pk2(hi_bf(sacc[2*kbk+1][0]), hi_bf(sacc[2*kbk+1][1]));
            aH[3] = pk2(hi_bf(sacc[2*kbk+1][2]), hi_bf(sacc[2*kbk+1][3]));
            aL[0] = pk2(lo_bf(sacc[2*kbk][0]),   lo_bf(sacc[2*kbk][1]));
            aL[1] = pk2(lo_bf(sacc[2*kbk][2]),   lo_bf(sacc[2*kbk][3]));
            aL[2] = pk2(lo_bf(sacc[2*kbk+1][0]), lo_bf(sacc[2*kbk+1][1]));
            aL[3] = pk2(lo_bf(sacc[2*kbk+1][2]), lo_bf(sacc[2*kbk+1][3]));

            uint32_t vh[4][4], vl[4][4];
            #pragma unroll
            for (int p = 0; p < 4; p++) {
                ldsm_x4(vh[p], bV + p * (16 * VROW) + kbk * 32);
                ldsm_x4(vl[p], bV + 128 + p * (16 * VROW) + kbk * 32);
            }
            #pragma unroll
            for (int nt = 0; nt < 8; nt++) {
                int p = nt >> 1, hh = (nt & 1) * 2;
                mma16816(oacc[nt], aH, vh[p][hh], vh[p][hh + 1]);
                mma16816(oacc[nt], aH, vl[p][hh], vl[p][hh + 1]);
                mma16816(oacc[nt], aL, vh[p][hh], vh[p][hh + 1]);
            }
        }
    }

    // epilogue: y/l + residual x -> x1
    #pragma unroll
    for (int h2 = 0; h2 < 2; h2++) {
        float inv = 1.f / l_[h2];
        int row = b * TLEN + q0 + 16 * w + g + 8 * h2;
        const float* xr = x  + (size_t)row * EMB + h * 64;
        float*       xo = x1 + (size_t)row * EMB + h * 64;
        #pragma unroll
        for (int nt = 0; nt < 8; nt++) {
            int c = nt * 8 + t4 * 2;
            float2 xv = *(const float2*)(xr + c);
            float2 yv;
            yv.x = oacc[nt][h2 * 2]     * inv + xv.x;
            yv.y = oacc[nt][h2 * 2 + 1] * inv + xv.y;
            *(float2*)(xo + c) = yv;
        }
    }
}

// ------------------------------------------------------------------
extern "C" void kernel_launch(void* const* d_in, const int* in_sizes, int n_in,
                              void* d_out, int out_size)
{
    const float* x      = (const float*)d_in[0];
    const float* ln1s   = (const float*)d_in[1];
    const float* ln1b   = (const float*)d_in[2];
    const float* w_qkv  = (const float*)d_in[3];
    const float* b_qkv  = (const float*)d_in[4];
    const float* ln2s   = (const float*)d_in[5];
    const float* ln2b   = (const float*)d_in[6];
    const float* w_fc   = (const float*)d_in[7];
    const float* b_fc   = (const float*)d_in[8];
    const float* w_proj = (const float*)d_in[9];
    const float* b_proj = (const float*)d_in[10];
    float* out = (float*)d_out;

    float *qkv, *x1;
    bf16 *lnh, *lnl, *wh, *wl, *a3h, *a3l, *q3, *k3, *v3;
    cudaGetSymbolAddress((void**)&qkv, g_qkv);
    cudaGetSymbolAddress((void**)&x1,  g_x1);
    cudaGetSymbolAddress((void**)&lnh, g_lnh);
    cudaGetSymbolAddress((void**)&lnl, g_lnl);
    cudaGetSymbolAddress((void**)&wh,  g_wh);
    cudaGetSymbolAddress((void**)&wl,  g_wl);
    cudaGetSymbolAddress((void**)&a3h, g_a3h);
    cudaGetSymbolAddress((void**)&a3l, g_a3l);
    cudaGetSymbolAddress((void**)&q3,  g_q3);
    cudaGetSymbolAddress((void**)&k3,  g_k3);
    cudaGetSymbolAddress((void**)&v3,  g_v3);

    cudaFuncSetAttribute(attn_hmma, cudaFuncAttributeMaxDynamicSharedMemorySize, ASMEM);
    cudaFuncSetAttribute(gemm_tc<false,false,false,true>,  cudaFuncAttributeMaxDynamicSharedMemorySize, GSMEM);
    cudaFuncSetAttribute(gemm_tc<true,false,true,false>,   cudaFuncAttributeMaxDynamicSharedMemorySize, GSMEM);
    cudaFuncSetAttribute(gemm_tc<false,true,false,false>,  cudaFuncAttributeMaxDynamicSharedMemorySize, GSMEM);

    // 1. lnh/lnl = split(LN1(x))
    ln_split<<<MROWS, 256>>>(x, ln1s, ln1b, lnh, lnl);
    // 2. qkv GEMM: Q/K packed straight to q3/k3; V region fp32 into qkv buffer
    convert_wt<<<dim3(EMB / 32, 3 * EMB / 32), dim3(32, 32)>>>(w_qkv, wh, wl, EMB, 3 * EMB);
    gemm_tc<false,false,false,true><<<dim3(3 * EMB / 128, MROWS / 128), 256, GSMEM>>>(
        lnh, lnl, wh, wl, b_qkv, nullptr, qkv, q3, k3, 3 * EMB, EMB);
    // 3. split/transpose V only
    prep_v<<<dim3(TLEN / 64, 32), 256>>>(qkv, v3);
    // 4. x1 = x + attention  (fused residual, global heavy-first order)
    attn_hmma<<<(TLEN / 128) * 32, 256, ASMEM>>>(q3, k3, v3, x, x1);
    // 5. lnh/lnl = split(LN2(x1))
    ln_split<<<MROWS, 256>>>(x1, ln2s, ln2b, lnh, lnl);
    // 6. a3h/a3l = split(relu(ln2 @ w_fc + b_fc))
    convert_wt<<<dim3(EMB / 32, HID / 32), dim3(32, 32)>>>(w_fc, wh, wl, EMB, HID);
    gemm_tc<true,false,true,false><<<dim3(HID / 128, MROWS / 128), 256, GSMEM>>>(
        lnh, lnl, wh, wl, b_fc, nullptr, nullptr, a3h, a3l, HID, EMB);
    // 7. out = x1 + fc @ w_proj + b_proj
    convert_wt<<<dim3(HID / 32, EMB / 32), dim3(32, 32)>>>(w_proj, wh, wl, HID, EMB);
    gemm_tc<false,true,false,false><<<dim3(EMB / 128, MROWS / 128), 256, GSMEM>>>(
        a3h, a3l, wh, wl, b_proj, x1, out, nullptr, nullptr, EMB, HID);
}

// round 16
// speedup vs baseline: 1.5629x; 1.0049x over previous
#include <cuda_runtime.h>
#include <cuda_bf16.h>
#include <math.h>
#include <stdint.h>

#define BATCH 2
#define TLEN  2048
#define EMB   1024
#define NHEAD 16
#define HDIM  64
#define MROWS (BATCH*TLEN)   /* 4096 */
#define HID   (4*EMB)        /* 4096 */

typedef __nv_bfloat16 bf16;

// ---- scratch (device globals; no allocation allowed) ----
__device__ float g_qkv[(size_t)MROWS * 3 * EMB];          // only V region used now
__device__ float g_x1 [(size_t)MROWS * EMB];
__device__ bf16  g_lnh[(size_t)MROWS * EMB];
__device__ bf16  g_lnl[(size_t)MROWS * EMB];
__device__ bf16  g_wh [(size_t)4194304];
__device__ bf16  g_wl [(size_t)4194304];
__device__ bf16  g_a3h[(size_t)MROWS * HID];
__device__ bf16  g_a3l[(size_t)MROWS * HID];
__device__ bf16  g_q3 [(size_t)32 * TLEN * 192];
__device__ bf16  g_k3 [(size_t)32 * TLEN * 192];
__device__ bf16  g_v3 [(size_t)32 * HDIM * 4096];

__device__ __forceinline__ uint32_t smem_u32(const void* p) {
    uint32_t a;
    asm("{ .reg .u64 t; cvta.to.shared.u64 t, %1; cvt.u32.u64 %0, t; }" : "=r"(a) : "l"(p));
    return a;
}
__device__ __forceinline__ void cp16(uint32_t saddr, const void* gaddr) {
    asm volatile("cp.async.cg.shared.global [%0], [%1], 16;" :: "r"(saddr), "l"(gaddr) : "memory");
}
__device__ __forceinline__ void ldsm_x4(uint32_t* r, uint32_t addr) {
    asm volatile("ldmatrix.sync.aligned.m8n8.x4.shared.b16 {%0,%1,%2,%3}, [%4];"
                 : "=r"(r[0]), "=r"(r[1]), "=r"(r[2]), "=r"(r[3]) : "r"(addr));
}
__device__ __forceinline__ void mma16816(float* c, const uint32_t* a, uint32_t b0, uint32_t b1) {
    asm volatile(
        "mma.sync.aligned.m16n8k16.row.col.f32.bf16.bf16.f32 "
        "{%0,%1,%2,%3}, {%4,%5,%6,%7}, {%8,%9}, {%0,%1,%2,%3};"
        : "+f"(c[0]), "+f"(c[1]), "+f"(c[2]), "+f"(c[3])
        : "r"(a[0]), "r"(a[1]), "r"(a[2]), "r"(a[3]), "r"(b0), "r"(b1));
}
__device__ __forceinline__ uint32_t pk2(bf16 a, bf16 b) {
    return (uint32_t)__bfloat16_as_ushort(a) | ((uint32_t)__bfloat16_as_ushort(b) << 16);
}
__device__ __forceinline__ void split2(float v, bf16& hi, bf16& lo) {
    hi = __float2bfloat16(v);
    lo = __float2bfloat16(v - __bfloat162float(hi));
}
__device__ __forceinline__ bf16 hi_bf(float v) { return __float2bfloat16(v); }
__device__ __forceinline__ bf16 lo_bf(float v) {
    bf16 h = __float2bfloat16(v);
    return __float2bfloat16(v - __bfloat162float(h));
}

// ------------------------------------------------------------------
// Weight conversion: W[K,N] f32 -> hi/lo planes [N,K] (transposed)
// ------------------------------------------------------------------
__global__ __launch_bounds__(1024) void convert_wt(
    const float* __restrict__ W, bf16* __restrict__ wh, bf16* __restrict__ wl,
    int K, int N)
{
    __shared__ float t[32][33];
    int tx = threadIdx.x, ty = threadIdx.y;
    int k0 = blockIdx.x * 32, n0 = blockIdx.y * 32;
    t[ty][tx] = W[(size_t)(k0 + ty) * N + n0 + tx];
    __syncthreads();
    float w = t[tx][ty];
    bf16 hi, lo; split2(w, hi, lo);
    size_t o = (size_t)(n0 + ty) * K + (k0 + tx);
    wh[o] = hi; wl[o] = lo;
}

// ------------------------------------------------------------------
// LayerNorm fused with activation split -> hi/lo planes [M,K]
// ------------------------------------------------------------------
__global__ __launch_bounds__(256) void ln_split(
    const float* __restrict__ x, const float* __restrict__ scale,
    const float* __restrict__ shift, bf16* __restrict__ lnh, bf16* __restrict__ lnl)
{
    int row = blockIdx.x;
    int t = threadIdx.x;
    const float4* xr = (const float4*)(x + (size_t)row * EMB);
    float4 v = xr[t];
    float s  = v.x + v.y + v.z + v.w;
    float sq = v.x*v.x + v.y*v.y + v.z*v.z + v.w*v.w;

    __shared__ float red[16];
    __shared__ float mv[2];
    #pragma unroll
    for (int o = 16; o > 0; o >>= 1) {
        s  += __shfl_xor_sync(0xffffffffu, s,  o);
        sq += __shfl_xor_sync(0xffffffffu, sq, o);
    }
    if ((t & 31) == 0) { red[t >> 5] = s; red[8 + (t >> 5)] = sq; }
    __syncthreads();
    if (t == 0) {
        float S = 0.f, SQ = 0.f;
        #pragma unroll
        for (int i = 0; i < 8; i++) { S += red[i]; SQ += red[8 + i]; }
        float mean = S * (1.0f / EMB);
        float var  = SQ * (1.0f / EMB) - mean * mean;
        mv[0] = mean; mv[1] = rsqrtf(var + 1e-5f);
    }
    __syncthreads();
    float mean = mv[0], inv = mv[1];
    float4 sc = ((const float4*)scale)[t];
    float4 sh = ((const float4*)shift)[t];
    float o0 = (v.x - mean) * inv * sc.x + sh.x;
    float o1 = (v.y - mean) * inv * sc.y + sh.y;
    float o2 = (v.z - mean) * inv * sc.z + sh.z;
    float o3 = (v.w - mean) * inv * sc.w + sh.w;
    bf16 h0,l0,h1,l1,h2,l2,h3,l3;
    split2(o0,h0,l0); split2(o1,h1,l1); split2(o2,h2,l2); split2(o3,h3,l3);
    uint32_t* ph = (uint32_t*)(lnh + (size_t)row * EMB) + 2 * t;
    ph[0] = pk2(h0,h1); ph[1] = pk2(h2,h3);
    uint32_t* pl = (uint32_t*)(lnl + (size_t)row * EMB) + 2 * t;
    pl[0] = pk2(l0,l1); pl[1] = pk2(l2,l3);
}

// ------------------------------------------------------------------
// prep_v: V only — transpose + hi/lo plane split
// ------------------------------------------------------------------
__global__ __launch_bounds__(256) void prep_v(
    const float* __restrict__ qkv, bf16* __restrict__ v3)
{
    __shared__ float vt[64][65];
    int bh = blockIdx.y;
    int tt = blockIdx.x;
    int b = bh >> 4, h = bh & 15;
    int t0 = tt * 64;
    int tid = threadIdx.x;
    int r = tid >> 2, cc = (tid & 3) * 16;
    const float* base = qkv + ((size_t)(b * TLEN + t0 + r)) * 3072 + 2048 + h * 64;

    float vv[16];
    #pragma unroll
    for (int j = 0; j < 4; j++)
        *(float4*)(vv + 4 * j) = *(const float4*)(base + cc + 4 * j);

    #pragma unroll
    for (int j = 0; j < 16; j++) vt[cc + j][r] = vv[j];
    __syncthreads();
    {
        uint32_t oh[8], ol[8];
        #pragma unroll
        for (int j = 0; j < 16; j += 2) {
            bf16 a0,b0,a1,b1;
            split2(vt[r][cc + j], a0, b0); split2(vt[r][cc + j + 1], a1, b1);
            oh[j >> 1] = pk2(a0, a1);
            ol[j >> 1] = pk2(b0, b1);
        }
        bf16* vrow = v3 + ((size_t)bh * 64 + r) * 4096 + (size_t)tt * 128;
        uint4* dh = (uint4*)(vrow + cc);
        dh[0] = ((uint4*)oh)[0]; dh[1] = ((uint4*)oh)[1];
        uint4* dl = (uint4*)(vrow + 64 + cc);
        dl[0] = ((uint4*)ol)[0]; dl[1] = ((uint4*)ol)[1];
    }
}

// ------------------------------------------------------------------
// HMMA GEMM, plane-segmented triple split.
// BM=128 BN=128 BK=64, 3-stage cp.async, 128 threads = 4 warps (2x2),
// warp tile 64x64, occupancy 2 (reg budget 256/thread at 128 thr).
// ------------------------------------------------------------------
#define ROWB   144
#define TILEB  (128*ROWB)      /* 18432 */
#define STAGEB (2*TILEB)       /* 36864 */
#define GSMEM  (3*STAGEB)      /* 110592 */

template<bool RELU, bool HASRES, bool WSPLIT, bool QKPACK>
__global__ __launch_bounds__(128, 2)
void gemm_tc(const bf16* __restrict__ Ah, const bf16* __restrict__ Al,
             const bf16* __restrict__ Bh, const bf16* __restrict__ Bl,
             const float* __restrict__ bias, const float* __restrict__ res,
             float* __restrict__ C, bf16* __restrict__ C3h, bf16* __restrict__ C3l,
             int N, int K)
{
    extern __shared__ __align__(128) unsigned char smem[];
    uint32_t sb = smem_u32(smem);
    int tid = threadIdx.x, w = tid >> 5, l = tid & 31;
    int wm = w >> 1, wn = w & 1;
    int m0 = blockIdx.y * 128, n0 = blockIdx.x * 128;
    int KC = K >> 6;
    int NCH = 3 * KC;

    const bf16* Ahb = Ah + (size_t)m0 * K;
    const bf16* Alb = Al + (size_t)m0 * K;
    const bf16* Bhb = Bh + (size_t)n0 * K;
    const bf16* Blb = Bl + (size_t)n0 * K;

    // loader: per tile 128 rows x 8 chunks(16B) = 1024; 8 per thread (128 thr)
    int lrow[8], lch[8];
    #pragma unroll
    for (int i = 0; i < 8; i++) {
        int idx = tid + i * 128;
        lrow[i] = idx >> 3; lch[i] = idx & 7;
    }

    uint32_t aBase = sb + (uint32_t)((wm * 64 + ((l >> 3) & 1) * 8 + (l & 7)) * ROWB + (l >> 4) * 16);
    uint32_t bBase = sb + TILEB + (uint32_t)((wn * 64 + (l >> 4) * 8 + (l & 7)) * ROWB + ((l >> 3) & 1) * 16);

    float acc[4][8][4];
    #pragma unroll
    for (int i = 0; i < 4; i++)
        #pragma unroll
        for (int j = 0; j < 8; j++)
            #pragma unroll
            for (int q = 0; q < 4; q++) acc[i][j][q] = 0.f;

    // prologue: chunks 0,1 (both in segment 0 since KC >= 16)
    #pragma unroll
    for (int s = 0; s < 2; s++) {
        size_t kc = (size_t)s * 64;
        #pragma unroll
        for (int i = 0; i < 8; i++) {
            uint32_t so = (uint32_t)(s * STAGEB + lrow[i] * ROWB + lch[i] * 16);
            cp16(sb + so,         Ahb + (size_t)lrow[i] * K + kc + lch[i] * 8);
            cp16(sb + TILEB + so, Bhb + (size_t)lrow[i] * K + kc + lch[i] * 8);
        }
        asm volatile("cp.async.commit_group;" ::: "memory");
    }

    for (int c = 0; c < NCH; c++) {
        asm volatile("cp.async.wait_group 1;" ::: "memory");
        __syncthreads();
        int nc = c + 2;
        if (nc < NCH) {
            int buf = nc % 3;
            int seg = (nc >= KC) + (nc >= 2 * KC);
            int kk = nc - seg * KC;
            const bf16* Asrc = (seg == 2) ? Alb : Ahb;
            const bf16* Bsrc = (seg == 1) ? Blb : Bhb;
            size_t kc = (size_t)kk * 64;
            #pragma unroll
            for (int i = 0; i < 8; i++) {
                uint32_t so = (uint32_t)(buf * STAGEB + lrow[i] * ROWB + lch[i] * 16);
                cp16(sb + so,         Asrc + (size_t)lrow[i] * K + kc + lch[i] * 8);
                cp16(sb + TILEB + so, Bsrc + (size_t)lrow[i] * K + kc + lch[i] * 8);
            }
        }
        asm volatile("cp.async.commit_group;" ::: "memory");

        uint32_t as0 = aBase + (uint32_t)((c % 3) * STAGEB);
        uint32_t bs0 = bBase + (uint32_t)((c % 3) * STAGEB);
        #pragma unroll
        for (int ks = 0; ks < 4; ks++) {
            uint32_t ar[4][4], br[4][4];
            #pragma unroll
            for (int mt = 0; mt < 4; mt++)
                ldsm_x4(ar[mt], as0 + mt * (16 * ROWB) + ks * 32);
            #pragma unroll
            for (int p = 0; p < 4; p++)
                ldsm_x4(br[p], bs0 + p * (16 * ROWB) + ks * 32);
            #pragma unroll
            for (int mt = 0; mt < 4; mt++) {
                #pragma unroll
                for (int nt = 0; nt < 8; nt++) {
                    int p = nt >> 1, hh = (nt & 1) * 2;
                    mma16816(acc[mt][nt], ar[mt], br[p][hh], br[p][hh + 1]);
                }
            }
        }
    }

    // epilogue
    int g = l >> 2, t4 = l & 3;
    int region = n0 >> 10;   // 0=Q, 1=K, 2=V (for QKPACK)
    #pragma unroll
    for (int mt = 0; mt < 4; mt++) {
        int row0 = m0 + wm * 64 + mt * 16 + g;
        #pragma unroll
        for (int nt = 0; nt < 8; nt++) {
            int col = n0 + wn * 64 + nt * 8 + t4 * 2;
            float2 bv = *(const float2*)(bias + col);
            float v0 = acc[mt][nt][0] + bv.x;
            float v1 = acc[mt][nt][1] + bv.y;
            float v2 = acc[mt][nt][2] + bv.x;
            float v3 = acc[mt][nt][3] + bv.y;
            if (RELU) {
                v0 = fmaxf(v0, 0.f); v1 = fmaxf(v1, 0.f);
                v2 = fmaxf(v2, 0.f); v3 = fmaxf(v3, 0.f);
            }
            if (QKPACK && region < 2) {
                int hcol = (col >> 6) & 15;
                int dd = col & 63;
                int bb = row0 >> 11, tt0 = row0 & 2047;
                bf16* dst = (region == 0) ? C3h : C3l;   // q3 : k3
                size_t base = ((size_t)(bb * 16 + hcol) * TLEN + tt0) * 192 + 3 * dd;
                bf16 a0,b0,a1,b1;
                split2(v0,a0,b0); split2(v1,a1,b1);
                uint32_t* p = (uint32_t*)(dst + base);
                if (region == 0) { p[0] = pk2(a0,a0); p[1] = pk2(b0,a1); p[2] = pk2(a1,b1); }
                else             { p[0] = pk2(a0,b0); p[1] = pk2(a0,a1); p[2] = pk2(b1,a1); }
                split2(v2,a0,b0); split2(v3,a1,b1);
                uint32_t* q = (uint32_t*)(dst + base + 8 * 192);
                if (region == 0) { q[0] = pk2(a0,a0); q[1] = pk2(b0,a1); q[2] = pk2(a1,b1); }
                else             { q[0] = pk2(a0,b0); q[1] = pk2(a0,a1); q[2] = pk2(b1,a1); }
            } else if (WSPLIT) {
                bf16 h0,l0,h1,l1;
                split2(v0,h0,l0); split2(v1,h1,l1);
                *(uint32_t*)(C3h + (size_t)row0 * N + col) = pk2(h0,h1);
                *(uint32_t*)(C3l + (size_t)row0 * N + col) = pk2(l0,l1);
                split2(v2,h0,l0); split2(v3,h1,l1);
                *(uint32_t*)(C3h + (size_t)(row0 + 8) * N + col) = pk2(h0,h1);
                *(uint32_t*)(C3l + (size_t)(row0 + 8) * N + col) = pk2(l0,l1);
            } else {
                if (HASRES) {
                    float2 r1 = *(const float2*)(res + (size_t)row0 * N + col);
                    float2 r2 = *(const float2*)(res + (size_t)(row0 + 8) * N + col);
                    v0 += r1.x; v1 += r1.y; v2 += r2.x; v3 += r2.y;
                }
                *(float2*)(C + (size_t)row0 * N + col)       = make_float2(v0, v1);
                *(float2*)(C + (size_t)(row0 + 8) * N + col) = make_float2(v2, v3);
            }
        }
    }
}

// ------------------------------------------------------------------
// HMMA flash attention (causal), triple-split bf16, registers-direct P,
// Q fragments hoisted to registers (loop-invariant).
// 1-D grid, GLOBAL heavy-first ordering: qi = 15 - bid/32, bh = bid%32.
// ------------------------------------------------------------------
#define LDROW 400
#define VROW  272
#define AQ_OFF   0u
#define AK_OFF   51200u
#define AV_OFF   102400u
#define ASMEM    137216

__global__ __launch_bounds__(256) void attn_hmma(
    const bf16* __restrict__ q3, const bf16* __restrict__ k3,
    const bf16* __restrict__ v3, const float* __restrict__ x,
    float* __restrict__ x1)
{
    extern __shared__ __align__(128) unsigned char sm[];
    uint32_t sb = smem_u32(sm);
    int tid = threadIdx.x, w = tid >> 5, l = tid & 31;
    int g = l >> 2, t4 = l & 3;
    int bid = blockIdx.x;
    int bh = bid & 31;
    int qi = (TLEN / 128 - 1) - (bid >> 5);
    int b = bh >> 4, h = bh & 15;
    int q0 = qi * 128;
    int ktn = 2 * qi + 2;

    const bf16* qb = q3 + ((size_t)bh * TLEN + q0) * 192;
    const bf16* kb = k3 + (size_t)bh * TLEN * 192;
    const bf16* vb = v3 + (size_t)bh * 64 * 4096;

    for (int i = tid; i < 3072; i += 256) {
        int r = i / 24, c = i % 24;
        cp16(sb + AQ_OFF + r * LDROW + c * 16, qb + (size_t)r * 192 + c * 8);
    }
    asm volatile("cp.async.commit_group;" ::: "memory");
    for (int i = tid; i < 1536; i += 256) {
        int r = i / 24, c = i % 24;
        cp16(sb + AK_OFF + r * LDROW + c * 16, kb + (size_t)r * 192 + c * 8);
    }
    for (int i = tid; i < 1024; i += 256) {
        int r = i >> 4, c = i & 15;
        cp16(sb + AV_OFF + r * VROW + c * 16, vb + (size_t)r * 4096 + c * 8);
    }
    asm volatile("cp.async.commit_group;" ::: "memory");

    uint32_t rowPartA = (uint32_t)((16 * w + ((l >> 3) & 1) * 8 + (l & 7)) * LDROW + (l >> 4) * 16);
    uint32_t aQ = sb + AQ_OFF + rowPartA;
    uint32_t bPartK = (uint32_t)(((l >> 4) * 8 + (l & 7)) * LDROW + ((l >> 3) & 1) * 16);
    uint32_t bPartV = (uint32_t)(((l >> 4) * 8 + (l & 7)) * VROW + ((l >> 3) & 1) * 16);

    float m_[2] = {-1e30f, -1e30f};
    float l_[2] = {0.f, 0.f};
    float oacc[8][4];
    #pragma unroll
    for (int nt = 0; nt < 8; nt++)
        #pragma unroll
        for (int q = 0; q < 4; q++) oacc[nt][q] = 0.f;

    uint32_t qr[12][4];

    for (int kt = 0; kt < ktn; kt++) {
        asm volatile("cp.async.wait_group 0;" ::: "memory");
        __syncthreads();
        if (kt == 0) {
            #pragma unroll
            for (int ks = 0; ks < 12; ks++)
                ldsm_x4(qr[ks], aQ + ks * 32);
        }
        if (kt + 1 < ktn) {
            uint32_t kboff = ((kt + 1) & 1) * 25600u;
            uint32_t vboff = ((kt + 1) & 1) * 17408u;
            for (int i = tid; i < 1536; i += 256) {
                int r = i / 24, c = i % 24;
                cp16(sb + AK_OFF + kboff + r * LDROW + c * 16,
                     kb + ((size_t)(kt + 1) * 64 + r) * 192 + c * 8);
            }
            for (int i = tid; i < 1024; i += 256) {
                int r = i >> 4, c = i & 15;
                cp16(sb + AV_OFF + vboff + r * VROW + c * 16,
                     vb + (size_t)r * 4096 + (size_t)(kt + 1) * 128 + c * 8);
            }
        }
        asm volatile("cp.async.commit_group;" ::: "memory");

        uint32_t bK = sb + AK_OFF + (kt & 1) * 25600u + bPartK;
        uint32_t bV = sb + AV_OFF + (kt & 1) * 17408u + bPartV;

        float sacc[8][4];
        #pragma unroll
        for (int nt = 0; nt < 8; nt++)
            #pragma unroll
            for (int q = 0; q < 4; q++) sacc[nt][q] = 0.f;
        #pragma unroll
        for (int ks = 0; ks < 12; ks++) {
            uint32_t br[4][4];
            #pragma unroll
            for (int p = 0; p < 4; p++)
                ldsm_x4(br[p], bK + p * (16 * LDROW) + ks * 32);
            #pragma unroll
            for (int nt = 0; nt < 8; nt++)
                mma16816(sacc[nt], qr[ks], br[nt >> 1][(nt & 1) * 2], br[nt >> 1][(nt & 1) * 2 + 1]);
        }

        int k0 = kt * 64;
        if (k0 + 63 > q0) {
            int r0 = q0 + 16 * w + g, r1 = r0 + 8;
            #pragma unroll
            for (int nt = 0; nt < 8; nt++) {
                int c0 = k0 + nt * 8 + t4 * 2;
                sacc[nt][0] = (c0     > r0) ? -1e30f : sacc[nt][0] * 0.125f;
                sacc[nt][1] = (c0 + 1 > r0) ? -1e30f : sacc[nt][1] * 0.125f;
                sacc[nt][2] = (c0     > r1) ? -1e30f : sacc[nt][2] * 0.125f;
                sacc[nt][3] = (c0 + 1 > r1) ? -1e30f : sacc[nt][3] * 0.125f;
            }
        } else {
            #pragma unroll
            for (int nt = 0; nt < 8; nt++)
                #pragma unroll
                for (int q = 0; q < 4; q++) sacc[nt][q] *= 0.125f;
        }

        #pragma unroll
        for (int h2 = 0; h2 < 2; h2++) {
            float mx = -1e30f;
            #pragma unroll
            for (int nt = 0; nt < 8; nt++)
                mx = fmaxf(mx, fmaxf(sacc[nt][h2 * 2], sacc[nt][h2 * 2 + 1]));
            mx = fmaxf(mx, __shfl_xor_sync(0xffffffffu, mx, 1));
            mx = fmaxf(mx, __shfl_xor_sync(0xffffffffu, mx, 2));
            float mn = fmaxf(m_[h2], mx);
            float al = __expf(m_[h2] - mn);
            float sum = 0.f;
            #pragma unroll
            for (int nt = 0; nt < 8; nt++) {
                float p0 = __expf(sacc[nt][h2 * 2]     - mn);
                float p1 = __expf(sacc[nt][h2 * 2 + 1] - mn);
                sacc[nt][h2 * 2] = p0; sacc[nt][h2 * 2 + 1] = p1;
                sum += p0 + p1;
            }
            sum += __shfl_xor_sync(0xffffffffu, sum, 1);
            sum += __shfl_xor_sync(0xffffffffu, sum, 2);
            l_[h2] = l_[h2] * al + sum;
            m_[h2] = mn;
            #pragma unroll
            for (int nt = 0; nt < 8; nt++) {
                oacc[nt][h2 * 2]     *= al;
                oacc[nt][h2 * 2 + 1] *= al;
            }
        }

        #pragma unroll
        for (int kbk = 0; kbk < 4; kbk++) {
            uint32_t aH[4], aL[4];
            aH[0] = pk2(hi_bf(sacc[2*kbk][0]),   hi_bf(sacc[2*kbk][1]));
            aH[1] = pk2(hi_bf(sacc[2*kbk][2]),   hi_bf(sacc[2*kbk][3]));
            aH[2] = pk2(hi_bf(sacc[2*kbk+1][0]), hi_bf(sacc[2*kbk+1][1]));
            aH[3] = pk2(hi_bf(sacc[2*kbk+1][2]), hi_bf(sacc[2*kbk+1][3]));
            aL[0] = pk2(lo_bf(sacc[2*kbk][0]),   lo_bf(sacc[2*kbk][1]));
            aL[1] = pk2(lo_bf(sacc[2*kbk][2]),   lo_bf(sacc[2*kbk][3]));
            aL[2] = pk2(lo_bf(sacc[2*kbk+1][0]), lo_bf(sacc[2*kbk+1][1]));
            aL[3] = pk2(lo_bf(sacc[2*kbk+1][2]), lo_bf(sacc[2*kbk+1][3]));

            uint32_t vh[4][4], vl[4][4];
            #pragma unroll
            for (int p = 0; p < 4; p++) {
                ldsm_x4(vh[p], bV + p * (16 * VROW) + kbk * 32);
                ldsm_x4(vl[p], bV + 128 + p * (16 * VROW) + kbk * 32);
            }
            #pragma unroll
            for (int nt = 0; nt < 8; nt++) {
                int p = nt >> 1, hh = (nt & 1) * 2;
                mma16816(oacc[nt], aH, vh[p][hh], vh[p][hh + 1]);
                mma16816(oacc[nt], aH, vl[p][hh], vl[p][hh + 1]);
                mma16816(oacc[nt], aL, vh[p][hh], vh[p][hh + 1]);
            }
        }
    }

    #pragma unroll
    for (int h2 = 0; h2 < 2; h2++) {
        float inv = 1.f / l_[h2];
        int row = b * TLEN + q0 + 16 * w + g + 8 * h2;
        const float* xr = x  + (size_t)row * EMB + h * 64;
        float*       xo = x1 + (size_t)row * EMB + h * 64;
        #pragma unroll
        for (int nt = 0; nt < 8; nt++) {
            int c = nt * 8 + t4 * 2;
            float2 xv = *(const float2*)(xr + c);
            float2 yv;
            yv.x = oacc[nt][h2 * 2]     * inv + xv.x;
            yv.y = oacc[nt][h2 * 2 + 1] * inv + xv.y;
            *(float2*)(xo + c) = yv;
        }
    }
}

// ------------------------------------------------------------------
extern "C" void kernel_launch(void* const* d_in, const int* in_sizes, int n_in,
                              void* d_out, int out_size)
{
    const float* x      = (const float*)d_in[0];
    const float* ln1s   = (const float*)d_in[1];
    const float* ln1b   = (const float*)d_in[2];
    const float* w_qkv  = (const float*)d_in[3];
    const float* b_qkv  = (const float*)d_in[4];
    const float* ln2s   = (const float*)d_in[5];
    const float* ln2b   = (const float*)d_in[6];
    const float* w_fc   = (const float*)d_in[7];
    const float* b_fc   = (const float*)d_in[8];
    const float* w_proj = (const float*)d_in[9];
    const float* b_proj = (const float*)d_in[10];
    float* out = (float*)d_out;

    float *qkv, *x1;
    bf16 *lnh, *lnl, *wh, *wl, *a3h, *a3l, *q3, *k3, *v3;
    cudaGetSymbolAddress((void**)&qkv, g_qkv);
    cudaGetSymbolAddress((void**)&x1,  g_x1);
    cudaGetSymbolAddress((void**)&lnh, g_lnh);
    cudaGetSymbolAddress((void**)&lnl, g_lnl);
    cudaGetSymbolAddress((void**)&wh,  g_wh);
    cudaGetSymbolAddress((void**)&wl,  g_wl);
    cudaGetSymbolAddress((void**)&a3h, g_a3h);
    cudaGetSymbolAddress((void**)&a3l, g_a3l);
    cudaGetSymbolAddress((void**)&q3,  g_q3);
    cudaGetSymbolAddress((void**)&k3,  g_k3);
    cudaGetSymbolAddress((void**)&v3,  g_v3);

    cudaFuncSetAttribute(attn_hmma, cudaFuncAttributeMaxDynamicSharedMemorySize, ASMEM);
    cudaFuncSetAttribute(gemm_tc<false,false,false,true>,  cudaFuncAttributeMaxDynamicSharedMemorySize, GSMEM);
    cudaFuncSetAttribute(gemm_tc<true,false,true,false>,   cudaFuncAttributeMaxDynamicSharedMemorySize, GSMEM);
    cudaFuncSetAttribute(gemm_tc<false,true,false,false>,  cudaFuncAttributeMaxDynamicSharedMemorySize, GSMEM);

    // 1. lnh/lnl = split(LN1(x))
    ln_split<<<MROWS, 256>>>(x, ln1s, ln1b, lnh, lnl);
    // 2. qkv GEMM: Q/K packed straight to q3/k3; V region fp32 into qkv buffer
    convert_wt<<<dim3(EMB / 32, 3 * EMB / 32), dim3(32, 32)>>>(w_qkv, wh, wl, EMB, 3 * EMB);
    gemm_tc<false,false,false,true><<<dim3(3 * EMB / 128, MROWS / 128), 128, GSMEM>>>(
        lnh, lnl, wh, wl, b_qkv, nullptr, qkv, q3, k3, 3 * EMB, EMB);
    // 3. split/transpose V only
    prep_v<<<dim3(TLEN / 64, 32), 256>>>(qkv, v3);
    // 4. x1 = x + attention  (fused residual, global heavy-first order)
    attn_hmma<<<(TLEN / 128) * 32, 256, ASMEM>>>(q3, k3, v3, x, x1);
    // 5. lnh/lnl = split(LN2(x1))
    ln_split<<<MROWS, 256>>>(x1, ln2s, ln2b, lnh, lnl);
    // 6. a3h/a3l = split(relu(ln2 @ w_fc + b_fc))
    convert_wt<<<dim3(EMB / 32, HID / 32), dim3(32, 32)>>>(w_fc, wh, wl, EMB, HID);
    gemm_tc<true,false,true,false><<<dim3(HID / 128, MROWS / 128), 128, GSMEM>>>(
        lnh, lnl, wh, wl, b_fc, nullptr, nullptr, a3h, a3l, HID, EMB);
    // 7. out = x1 + fc @ w_proj + b_proj
    convert_wt<<<dim3(HID / 32, EMB / 32), dim3(32, 32)>>>(w_proj, wh, wl, HID, EMB);
    gemm_tc<false,true,false,false><<<dim3(EMB / 128, MROWS / 128), 128, GSMEM>>>(
        a3h, a3l, wh, wl, b_proj, x1, out, nullptr, nullptr, EMB, HID);
}

// round 17
// speedup vs baseline: 1.8263x; 1.1686x over previous
#include <cuda_runtime.h>
#include <cuda_bf16.h>
#include <cuda_fp16.h>
#include <math.h>
#include <stdint.h>

#define BATCH 2
#define TLEN  2048
#define EMB   1024
#define NHEAD 16
#define HDIM  64
#define MROWS (BATCH*TLEN)   /* 4096 */
#define HID   (4*EMB)        /* 4096 */

typedef __nv_bfloat16 bf16;
typedef __half f16;

// ---- scratch (device globals; no allocation allowed) ----
__device__ float g_qkv[(size_t)MROWS * 3 * EMB];          // only V region used now
__device__ float g_x1 [(size_t)MROWS * EMB];
__device__ bf16  g_lnh[(size_t)MROWS * EMB];              // LN split hi plane (bf16 or f16 bits)
__device__ bf16  g_lnl[(size_t)MROWS * EMB];              // LN split lo plane
__device__ bf16  g_wh [(size_t)4194304];                  // weight hi plane [N,K]
__device__ bf16  g_wl [(size_t)4194304];                  // weight lo plane [N,K]
__device__ bf16  g_a3h[(size_t)MROWS * HID];              // fc out hi plane (f16 bits)
__device__ bf16  g_a3l[(size_t)MROWS * HID];              // fc out lo plane (f16 bits)
__device__ bf16  g_q3 [(size_t)32 * TLEN * 192];
__device__ bf16  g_k3 [(size_t)32 * TLEN * 192];
__device__ bf16  g_v3 [(size_t)32 * HDIM * 4096];

__device__ __forceinline__ uint32_t smem_u32(const void* p) {
    uint32_t a;
    asm("{ .reg .u64 t; cvta.to.shared.u64 t, %1; cvt.u32.u64 %0, t; }" : "=r"(a) : "l"(p));
    return a;
}
__device__ __forceinline__ void cp16(uint32_t saddr, const void* gaddr) {
    asm volatile("cp.async.cg.shared.global [%0], [%1], 16;" :: "r"(saddr), "l"(gaddr) : "memory");
}
__device__ __forceinline__ void ldsm_x4(uint32_t* r, uint32_t addr) {
    asm volatile("ldmatrix.sync.aligned.m8n8.x4.shared.b16 {%0,%1,%2,%3}, [%4];"
                 : "=r"(r[0]), "=r"(r[1]), "=r"(r[2]), "=r"(r[3]) : "r"(addr));
}
__device__ __forceinline__ void mma16816(float* c, const uint32_t* a, uint32_t b0, uint32_t b1) {
    asm volatile(
        "mma.sync.aligned.m16n8k16.row.col.f32.bf16.bf16.f32 "
        "{%0,%1,%2,%3}, {%4,%5,%6,%7}, {%8,%9}, {%0,%1,%2,%3};"
        : "+f"(c[0]), "+f"(c[1]), "+f"(c[2]), "+f"(c[3])
        : "r"(a[0]), "r"(a[1]), "r"(a[2]), "r"(a[3]), "r"(b0), "r"(b1));
}
__device__ __forceinline__ void mma16816f(float* c, const uint32_t* a, uint32_t b0, uint32_t b1) {
    asm volatile(
        "mma.sync.aligned.m16n8k16.row.col.f32.f16.f16.f32 "
        "{%0,%1,%2,%3}, {%4,%5,%6,%7}, {%8,%9}, {%0,%1,%2,%3};"
        : "+f"(c[0]), "+f"(c[1]), "+f"(c[2]), "+f"(c[3])
        : "r"(a[0]), "r"(a[1]), "r"(a[2]), "r"(a[3]), "r"(b0), "r"(b1));
}
__device__ __forceinline__ uint32_t pk2(bf16 a, bf16 b) {
    return (uint32_t)__bfloat16_as_ushort(a) | ((uint32_t)__bfloat16_as_ushort(b) << 16);
}
__device__ __forceinline__ uint32_t pk2h(f16 a, f16 b) {
    return (uint32_t)__half_as_ushort(a) | ((uint32_t)__half_as_ushort(b) << 16);
}
__device__ __forceinline__ void split2(float v, bf16& hi, bf16& lo) {
    hi = __float2bfloat16(v);
    lo = __float2bfloat16(v - __bfloat162float(hi));
}
__device__ __forceinline__ void split2h(float v, f16& hi, f16& lo) {
    hi = __float2half(v);
    lo = __float2half(v - __half2float(hi));
}
__device__ __forceinline__ bf16 hi_bf(float v) { return __float2bfloat16(v); }
__device__ __forceinline__ bf16 lo_bf(float v) {
    bf16 h = __float2bfloat16(v);
    return __float2bfloat16(v - __bfloat162float(h));
}

// ------------------------------------------------------------------
// Weight conversion: W[K,N] f32 -> transposed planes [N,K].
// TRI: bf16 hi+lo planes.  !TRI: single fp16 plane (wh only).
// ------------------------------------------------------------------
template<bool TRI>
__global__ __launch_bounds__(1024) void convert_wt(
    const float* __restrict__ W, bf16* __restrict__ wh, bf16* __restrict__ wl,
    int K, int N)
{
    __shared__ float t[32][33];
    int tx = threadIdx.x, ty = threadIdx.y;
    int k0 = blockIdx.x * 32, n0 = blockIdx.y * 32;
    t[ty][tx] = W[(size_t)(k0 + ty) * N + n0 + tx];
    __syncthreads();
    float w = t[tx][ty];
    size_t o = (size_t)(n0 + ty) * K + (k0 + tx);
    if (TRI) {
        bf16 hi, lo; split2(w, hi, lo);
        wh[o] = hi; wl[o] = lo;
    } else {
        ((f16*)wh)[o] = __float2half(w);
    }
}

// ------------------------------------------------------------------
// LayerNorm fused with activation split -> hi/lo planes [M,K]
// TRI: bf16 planes.  !TRI: fp16 planes.
// ------------------------------------------------------------------
template<bool TRI>
__global__ __launch_bounds__(256) void ln_split(
    const float* __restrict__ x, const float* __restrict__ scale,
    const float* __restrict__ shift, bf16* __restrict__ lnh, bf16* __restrict__ lnl)
{
    int row = blockIdx.x;
    int t = threadIdx.x;
    const float4* xr = (const float4*)(x + (size_t)row * EMB);
    float4 v = xr[t];
    float s  = v.x + v.y + v.z + v.w;
    float sq = v.x*v.x + v.y*v.y + v.z*v.z + v.w*v.w;

    __shared__ float red[16];
    __shared__ float mv[2];
    #pragma unroll
    for (int o = 16; o > 0; o >>= 1) {
        s  += __shfl_xor_sync(0xffffffffu, s,  o);
        sq += __shfl_xor_sync(0xffffffffu, sq, o);
    }
    if ((t & 31) == 0) { red[t >> 5] = s; red[8 + (t >> 5)] = sq; }
    __syncthreads();
    if (t == 0) {
        float S = 0.f, SQ = 0.f;
        #pragma unroll
        for (int i = 0; i < 8; i++) { S += red[i]; SQ += red[8 + i]; }
        float mean = S * (1.0f / EMB);
        float var  = SQ * (1.0f / EMB) - mean * mean;
        mv[0] = mean; mv[1] = rsqrtf(var + 1e-5f);
    }
    __syncthreads();
    float mean = mv[0], inv = mv[1];
    float4 sc = ((const float4*)scale)[t];
    float4 sh = ((const float4*)shift)[t];
    float o0 = (v.x - mean) * inv * sc.x + sh.x;
    float o1 = (v.y - mean) * inv * sc.y + sh.y;
    float o2 = (v.z - mean) * inv * sc.z + sh.z;
    float o3 = (v.w - mean) * inv * sc.w + sh.w;
    uint32_t* ph = (uint32_t*)(lnh + (size_t)row * EMB) + 2 * t;
    uint32_t* pl = (uint32_t*)(lnl + (size_t)row * EMB) + 2 * t;
    if (TRI) {
        bf16 h0,l0,h1,l1,h2,l2,h3,l3;
        split2(o0,h0,l0); split2(o1,h1,l1); split2(o2,h2,l2); split2(o3,h3,l3);
        ph[0] = pk2(h0,h1); ph[1] = pk2(h2,h3);
        pl[0] = pk2(l0,l1); pl[1] = pk2(l2,l3);
    } else {
        f16 h0,l0,h1,l1,h2,l2,h3,l3;
        split2h(o0,h0,l0); split2h(o1,h1,l1); split2h(o2,h2,l2); split2h(o3,h3,l3);
        ph[0] = pk2h(h0,h1); ph[1] = pk2h(h2,h3);
        pl[0] = pk2h(l0,l1); pl[1] = pk2h(l2,l3);
    }
}

// ------------------------------------------------------------------
// prep_v: V only — transpose + hi/lo plane split (bf16, for attention)
// ------------------------------------------------------------------
__global__ __launch_bounds__(256) void prep_v(
    const float* __restrict__ qkv, bf16* __restrict__ v3)
{
    __shared__ float vt[64][65];
    int bh = blockIdx.y;
    int tt = blockIdx.x;
    int b = bh >> 4, h = bh & 15;
    int t0 = tt * 64;
    int tid = threadIdx.x;
    int r = tid >> 2, cc = (tid & 3) * 16;
    const float* base = qkv + ((size_t)(b * TLEN + t0 + r)) * 3072 + 2048 + h * 64;

    float vv[16];
    #pragma unroll
    for (int j = 0; j < 4; j++)
        *(float4*)(vv + 4 * j) = *(const float4*)(base + cc + 4 * j);

    #pragma unroll
    for (int j = 0; j < 16; j++) vt[cc + j][r] = vv[j];
    __syncthreads();
    {
        uint32_t oh[8], ol[8];
        #pragma unroll
        for (int j = 0; j < 16; j += 2) {
            bf16 a0,b0,a1,b1;
            split2(vt[r][cc + j], a0, b0); split2(vt[r][cc + j + 1], a1, b1);
            oh[j >> 1] = pk2(a0, a1);
            ol[j >> 1] = pk2(b0, b1);
        }
        bf16* vrow = v3 + ((size_t)bh * 64 + r) * 4096 + (size_t)tt * 128;
        uint4* dh = (uint4*)(vrow + cc);
        dh[0] = ((uint4*)oh)[0]; dh[1] = ((uint4*)oh)[1];
        uint4* dl = (uint4*)(vrow + 64 + cc);
        dl[0] = ((uint4*)ol)[0]; dl[1] = ((uint4*)ol)[1];
    }
}

// ------------------------------------------------------------------
// HMMA GEMM.
//  TRI:  C = Ah.Bh + Ah.Bl + Al.Bh  (bf16, 3 segments)
//  !TRI: C = Ah.B + Al.B            (fp16, 2 segments; B = wh single plane)
// BM=128 BN=128 BK=64, 3-stage cp.async, 128 threads = 4 warps (2x2),
// warp tile 64x64, occupancy 2.
// ------------------------------------------------------------------
#define ROWB   144
#define TILEB  (128*ROWB)
#define STAGEB (2*TILEB)
#define GSMEM  (3*STAGEB)

template<bool RELU, bool HASRES, bool WSPLIT, bool QKPACK, bool TRI>
__global__ __launch_bounds__(128, 2)
void gemm_tc(const bf16* __restrict__ Ah, const bf16* __restrict__ Al,
             const bf16* __restrict__ Bh, const bf16* __restrict__ Bl,
             const float* __restrict__ bias, const float* __restrict__ res,
             float* __restrict__ C, bf16* __restrict__ C3h, bf16* __restrict__ C3l,
             int N, int K)
{
    extern __shared__ __align__(128) unsigned char smem[];
    uint32_t sb = smem_u32(smem);
    int tid = threadIdx.x, w = tid >> 5, l = tid & 31;
    int wm = w >> 1, wn = w & 1;
    int m0 = blockIdx.y * 128, n0 = blockIdx.x * 128;
    int KC = K >> 6;
    int NCH = (TRI ? 3 : 2) * KC;

    const bf16* Ahb = Ah + (size_t)m0 * K;
    const bf16* Alb = Al + (size_t)m0 * K;
    const bf16* Bhb = Bh + (size_t)n0 * K;
    const bf16* Blb = Bl + (size_t)n0 * K;

    int lrow[8], lch[8];
    #pragma unroll
    for (int i = 0; i < 8; i++) {
        int idx = tid + i * 128;
        lrow[i] = idx >> 3; lch[i] = idx & 7;
    }

    uint32_t aBase = sb + (uint32_t)((wm * 64 + ((l >> 3) & 1) * 8 + (l & 7)) * ROWB + (l >> 4) * 16);
    uint32_t bBase = sb + TILEB + (uint32_t)((wn * 64 + (l >> 4) * 8 + (l & 7)) * ROWB + ((l >> 3) & 1) * 16);

    float acc[4][8][4];
    #pragma unroll
    for (int i = 0; i < 4; i++)
        #pragma unroll
        for (int j = 0; j < 8; j++)
            #pragma unroll
            for (int q = 0; q < 4; q++) acc[i][j][q] = 0.f;

    // prologue: chunks 0,1 (both in segment 0 since KC >= 16)
    #pragma unroll
    for (int s = 0; s < 2; s++) {
        size_t kc = (size_t)s * 64;
        #pragma unroll
        for (int i = 0; i < 8; i++) {
            uint32_t so = (uint32_t)(s * STAGEB + lrow[i] * ROWB + lch[i] * 16);
            cp16(sb + so,         Ahb + (size_t)lrow[i] * K + kc + lch[i] * 8);
            cp16(sb + TILEB + so, Bhb + (size_t)lrow[i] * K + kc + lch[i] * 8);
        }
        asm volatile("cp.async.commit_group;" ::: "memory");
    }

    for (int c = 0; c < NCH; c++) {
        asm volatile("cp.async.wait_group 1;" ::: "memory");
        __syncthreads();
        int nc = c + 2;
        if (nc < NCH) {
            int buf = nc % 3;
            const bf16* Asrc;
            const bf16* Bsrc;
            int kk;
            if (TRI) {
                int seg = (nc >= KC) + (nc >= 2 * KC);
                kk = nc - seg * KC;
                Asrc = (seg == 2) ? Alb : Ahb;
                Bsrc = (seg == 1) ? Blb : Bhb;
            } else {
                int seg = (nc >= KC);
                kk = nc - seg * KC;
                Asrc = seg ? Alb : Ahb;
                Bsrc = Bhb;
            }
            size_t kc = (size_t)kk * 64;
            #pragma unroll
            for (int i = 0; i < 8; i++) {
                uint32_t so = (uint32_t)(buf * STAGEB + lrow[i] * ROWB + lch[i] * 16);
                cp16(sb + so,         Asrc + (size_t)lrow[i] * K + kc + lch[i] * 8);
                cp16(sb + TILEB + so, Bsrc + (size_t)lrow[i] * K + kc + lch[i] * 8);
            }
        }
        asm volatile("cp.async.commit_group;" ::: "memory");

        uint32_t as0 = aBase + (uint32_t)((c % 3) * STAGEB);
        uint32_t bs0 = bBase + (uint32_t)((c % 3) * STAGEB);
        #pragma unroll
        for (int ks = 0; ks < 4; ks++) {
            uint32_t ar[4][4], br[4][4];
            #pragma unroll
            for (int mt = 0; mt < 4; mt++)
                ldsm_x4(ar[mt], as0 + mt * (16 * ROWB) + ks * 32);
            #pragma unroll
            for (int p = 0; p < 4; p++)
                ldsm_x4(br[p], bs0 + p * (16 * ROWB) + ks * 32);
            #pragma unroll
            for (int mt = 0; mt < 4; mt++) {
                #pragma unroll
                for (int nt = 0; nt < 8; nt++) {
                    int p = nt >> 1, hh = (nt & 1) * 2;
                    if (TRI) mma16816(acc[mt][nt], ar[mt], br[p][hh], br[p][hh + 1]);
                    else     mma16816f(acc[mt][nt], ar[mt], br[p][hh], br[p][hh + 1]);
                }
            }
        }
    }

    // epilogue
    int g = l >> 2, t4 = l & 3;
    int region = n0 >> 10;
    #pragma unroll
    for (int mt = 0; mt < 4; mt++) {
        int row0 = m0 + wm * 64 + mt * 16 + g;
        #pragma unroll
        for (int nt = 0; nt < 8; nt++) {
            int col = n0 + wn * 64 + nt * 8 + t4 * 2;
            float2 bv = *(const float2*)(bias + col);
            float v0 = acc[mt][nt][0] + bv.x;
            float v1 = acc[mt][nt][1] + bv.y;
            float v2 = acc[mt][nt][2] + bv.x;
            float v3 = acc[mt][nt][3] + bv.y;
            if (RELU) {
                v0 = fmaxf(v0, 0.f); v1 = fmaxf(v1, 0.f);
                v2 = fmaxf(v2, 0.f); v3 = fmaxf(v3, 0.f);
            }
            if (QKPACK && region < 2) {
                int hcol = (col >> 6) & 15;
                int dd = col & 63;
                int bb = row0 >> 11, tt0 = row0 & 2047;
                bf16* dst = (region == 0) ? C3h : C3l;
                size_t base = ((size_t)(bb * 16 + hcol) * TLEN + tt0) * 192 + 3 * dd;
                bf16 a0,b0,a1,b1;
                split2(v0,a0,b0); split2(v1,a1,b1);
                uint32_t* p = (uint32_t*)(dst + base);
                if (region == 0) { p[0] = pk2(a0,a0); p[1] = pk2(b0,a1); p[2] = pk2(a1,b1); }
                else             { p[0] = pk2(a0,b0); p[1] = pk2(a0,a1); p[2] = pk2(b1,a1); }
                split2(v2,a0,b0); split2(v3,a1,b1);
                uint32_t* q = (uint32_t*)(dst + base + 8 * 192);
                if (region == 0) { q[0] = pk2(a0,a0); q[1] = pk2(b0,a1); q[2] = pk2(a1,b1); }
                else             { q[0] = pk2(a0,b0); q[1] = pk2(a0,a1); q[2] = pk2(b1,a1); }
            } else if (WSPLIT) {
                // fp16 hi/lo plane output (consumed by non-TRI proj GEMM)
                f16 h0,l0,h1,l1;
                split2h(v0,h0,l0); split2h(v1,h1,l1);
                *(uint32_t*)(C3h + (size_t)row0 * N + col) = pk2h(h0,h1);
                *(uint32_t*)(C3l + (size_t)row0 * N + col) = pk2h(l0,l1);
                split2h(v2,h0,l0); split2h(v3,h1,l1);
                *(uint32_t*)(C3h + (size_t)(row0 + 8) * N + col) = pk2h(h0,h1);
                *(uint32_t*)(C3l + (size_t)(row0 + 8) * N + col) = pk2h(l0,l1);
            } else {
                if (HASRES) {
                    float2 r1 = *(const float2*)(res + (size_t)row0 * N + col);
                    float2 r2 = *(const float2*)(res + (size_t)(row0 + 8) * N + col);
                    v0 += r1.x; v1 += r1.y; v2 += r2.x; v3 += r2.y;
                }
                *(float2*)(C + (size_t)row0 * N + col)       = make_float2(v0, v1);
                *(float2*)(C + (size_t)(row0 + 8) * N + col) = make_float2(v2, v3);
            }
        }
    }
}

// ------------------------------------------------------------------
// HMMA flash attention (causal), triple-split bf16, registers-direct P,
// Q fragments hoisted. 1-D grid, global heavy-first ordering.
// ------------------------------------------------------------------
#define LDROW 400
#define VROW  272
#define AQ_OFF   0u
#define AK_OFF   51200u
#define AV_OFF   102400u
#define ASMEM    137216

__global__ __launch_bounds__(256) void attn_hmma(
    const bf16* __restrict__ q3, const bf16* __restrict__ k3,
    const bf16* __restrict__ v3, const float* __restrict__ x,
    float* __restrict__ x1)
{
    extern __shared__ __align__(128) unsigned char sm[];
    uint32_t sb = smem_u32(sm);
    int tid = threadIdx.x, w = tid >> 5, l = tid & 31;
    int g = l >> 2, t4 = l & 3;
    int bid = blockIdx.x;
    int bh = bid & 31;
    int qi = (TLEN / 128 - 1) - (bid >> 5);
    int b = bh >> 4, h = bh & 15;
    int q0 = qi * 128;
    int ktn = 2 * qi + 2;

    const bf16* qb = q3 + ((size_t)bh * TLEN + q0) * 192;
    const bf16* kb = k3 + (size_t)bh * TLEN * 192;
    const bf16* vb = v3 + (size_t)bh * 64 * 4096;

    for (int i = tid; i < 3072; i += 256) {
        int r = i / 24, c = i % 24;
        cp16(sb + AQ_OFF + r * LDROW + c * 16, qb + (size_t)r * 192 + c * 8);
    }
    asm volatile("cp.async.commit_group;" ::: "memory");
    for (int i = tid; i < 1536; i += 256) {
        int r = i / 24, c = i % 24;
        cp16(sb + AK_OFF + r * LDROW + c * 16, kb + (size_t)r * 192 + c * 8);
    }
    for (int i = tid; i < 1024; i += 256) {
        int r = i >> 4, c = i & 15;
        cp16(sb + AV_OFF + r * VROW + c * 16, vb + (size_t)r * 4096 + c * 8);
    }
    asm volatile("cp.async.commit_group;" ::: "memory");

    uint32_t rowPartA = (uint32_t)((16 * w + ((l >> 3) & 1) * 8 + (l & 7)) * LDROW + (l >> 4) * 16);
    uint32_t aQ = sb + AQ_OFF + rowPartA;
    uint32_t bPartK = (uint32_t)(((l >> 4) * 8 + (l & 7)) * LDROW + ((l >> 3) & 1) * 16);
    uint32_t bPartV = (uint32_t)(((l >> 4) * 8 + (l & 7)) * VROW + ((l >> 3) & 1) * 16);

    float m_[2] = {-1e30f, -1e30f};
    float l_[2] = {0.f, 0.f};
    float oacc[8][4];
    #pragma unroll
    for (int nt = 0; nt < 8; nt++)
        #pragma unroll
        for (int q = 0; q < 4; q++) oacc[nt][q] = 0.f;

    uint32_t qr[12][4];

    for (int kt = 0; kt < ktn; kt++) {
        asm volatile("cp.async.wait_group 0;" ::: "memory");
        __syncthreads();
        if (kt == 0) {
            #pragma unroll
            for (int ks = 0; ks < 12; ks++)
                ldsm_x4(qr[ks], aQ + ks * 32);
        }
        if (kt + 1 < ktn) {
            uint32_t kboff = ((kt + 1) & 1) * 25600u;
            uint32_t vboff = ((kt + 1) & 1) * 17408u;
            for (int i = tid; i < 1536; i += 256) {
                int r = i / 24, c = i % 24;
                cp16(sb + AK_OFF + kboff + r * LDROW + c * 16,
                     kb + ((size_t)(kt + 1) * 64 + r) * 192 + c * 8);
            }
            for (int i = tid; i < 1024; i += 256) {
                int r = i >> 4, c = i & 15;
                cp16(sb + AV_OFF + vboff + r * VROW + c * 16,
                     vb + (size_t)r * 4096 + (size_t)(kt + 1) * 128 + c * 8);
            }
        }
        asm volatile("cp.async.commit_group;" ::: "memory");

        uint32_t bK = sb + AK_OFF + (kt & 1) * 25600u + bPartK;
        uint32_t bV = sb + AV_OFF + (kt & 1) * 17408u + bPartV;

        float sacc[8][4];
        #pragma unroll
        for (int nt = 0; nt < 8; nt++)
            #pragma unroll
            for (int q = 0; q < 4; q++) sacc[nt][q] = 0.f;
        #pragma unroll
        for (int ks = 0; ks < 12; ks++) {
            uint32_t br[4][4];
            #pragma unroll
            for (int p = 0; p < 4; p++)
                ldsm_x4(br[p], bK + p * (16 * LDROW) + ks * 32);
            #pragma unroll
            for (int nt = 0; nt < 8; nt++)
                mma16816(sacc[nt], qr[ks], br[nt >> 1][(nt & 1) * 2], br[nt >> 1][(nt & 1) * 2 + 1]);
        }

        int k0 = kt * 64;
        if (k0 + 63 > q0) {
            int r0 = q0 + 16 * w + g, r1 = r0 + 8;
            #pragma unroll
            for (int nt = 0; nt < 8; nt++) {
                int c0 = k0 + nt * 8 + t4 * 2;
                sacc[nt][0] = (c0     > r0) ? -1e30f : sacc[nt][0] * 0.125f;
                sacc[nt][1] = (c0 + 1 > r0) ? -1e30f : sacc[nt][1] * 0.125f;
                sacc[nt][2] = (c0     > r1) ? -1e30f : sacc[nt][2] * 0.125f;
                sacc[nt][3] = (c0 + 1 > r1) ? -1e30f : sacc[nt][3] * 0.125f;
            }
        } else {
            #pragma unroll
            for (int nt = 0; nt < 8; nt++)
                #pragma unroll
                for (int q = 0; q < 4; q++) sacc[nt][q] *= 0.125f;
        }

        #pragma unroll
        for (int h2 = 0; h2 < 2; h2++) {
            float mx = -1e30f;
            #pragma unroll
            for (int nt = 0; nt < 8; nt++)
                mx = fmaxf(mx, fmaxf(sacc[nt][h2 * 2], sacc[nt][h2 * 2 + 1]));
            mx = fmaxf(mx, __shfl_xor_sync(0xffffffffu, mx, 1));
            mx = fmaxf(mx, __shfl_xor_sync(0xffffffffu, mx, 2));
            float mn = fmaxf(m_[h2], mx);
            float al = __expf(m_[h2] - mn);
            float sum = 0.f;
            #pragma unroll
            for (int nt = 0; nt < 8; nt++) {
                float p0 = __expf(sacc[nt][h2 * 2]     - mn);
                float p1 = __expf(sacc[nt][h2 * 2 + 1] - mn);
                sacc[nt][h2 * 2] = p0; sacc[nt][h2 * 2 + 1] = p1;
                sum += p0 + p1;
            }
            sum += __shfl_xor_sync(0xffffffffu, sum, 1);
            sum += __shfl_xor_sync(0xffffffffu, sum, 2);
            l_[h2] = l_[h2] * al + sum;
            m_[h2] = mn;
            #pragma unroll
            for (int nt = 0; nt < 8; nt++) {
                oacc[nt][h2 * 2]     *= al;
                oacc[nt][h2 * 2 + 1] *= al;
            }
        }

        #pragma unroll
        for (int kbk = 0; kbk < 4; kbk++) {
            uint32_t aH[4], aL[4];
            aH[0] = pk2(hi_bf(sacc[2*kbk][0]),   hi_bf(sacc[2*kbk][1]));
            aH[1] = pk2(hi_bf(sacc[2*kbk][2]),   hi_bf(sacc[2*kbk][3]));
            aH[2] = pk2(hi_bf(sacc[2*kbk+1][0]), hi_bf(sacc[2*kbk+1][1]));
            aH[3] = pk2(hi_bf(sacc[2*kbk+1][2]), hi_bf(sacc[2*kbk+1][3]));
            aL[0] = pk2(lo_bf(sacc[2*kbk][0]),   lo_bf(sacc[2*kbk][1]));
            aL[1] = pk2(lo_bf(sacc[2*kbk][2]),   lo_bf(sacc[2*kbk][3]));
            aL[2] = pk2(lo_bf(sacc[2*kbk+1][0]), lo_bf(sacc[2*kbk+1][1]));
            aL[3] = pk2(lo_bf(sacc[2*kbk+1][2]), lo_bf(sacc[2*kbk+1][3]));

            uint32_t vh[4][4], vl[4][4];
            #pragma unroll
            for (int p = 0; p < 4; p++) {
                ldsm_x4(vh[p], bV + p * (16 * VROW) + kbk * 32);
                ldsm_x4(vl[p], bV + 128 + p * (16 * VROW) + kbk * 32);
            }
            #pragma unroll
            for (int nt = 0; nt < 8; nt++) {
                int p = nt >> 1, hh = (nt & 1) * 2;
                mma16816(oacc[nt], aH, vh[p][hh], vh[p][hh + 1]);
                mma16816(oacc[nt], aH, vl[p][hh], vl[p][hh + 1]);
                mma16816(oacc[nt], aL, vh[p][hh], vh[p][hh + 1]);
            }
        }
    }

    #pragma unroll
    for (int h2 = 0; h2 < 2; h2++) {
        float inv = 1.f / l_[h2];
        int row = b * TLEN + q0 + 16 * w + g + 8 * h2;
        const float* xr = x  + (size_t)row * EMB + h * 64;
        float*       xo = x1 + (size_t)row * EMB + h * 64;
        #pragma unroll
        for (int nt = 0; nt < 8; nt++) {
            int c = nt * 8 + t4 * 2;
            float2 xv = *(const float2*)(xr + c);
            float2 yv;
            yv.x = oacc[nt][h2 * 2]     * inv + xv.x;
            yv.y = oacc[nt][h2 * 2 + 1] * inv + xv.y;
            *(float2*)(xo + c) = yv;
        }
    }
}

// ------------------------------------------------------------------
extern "C" void kernel_launch(void* const* d_in, const int* in_sizes, int n_in,
                              void* d_out, int out_size)
{
    const float* x      = (const float*)d_in[0];
    const float* ln1s   = (const float*)d_in[1];
    const float* ln1b   = (const float*)d_in[2];
    const float* w_qkv  = (const float*)d_in[3];
    const float* b_qkv  = (const float*)d_in[4];
    const float* ln2s   = (const float*)d_in[5];
    const float* ln2b   = (const float*)d_in[6];
    const float* w_fc   = (const float*)d_in[7];
    const float* b_fc   = (const float*)d_in[8];
    const float* w_proj = (const float*)d_in[9];
    const float* b_proj = (const float*)d_in[10];
    float* out = (float*)d_out;

    float *qkv, *x1;
    bf16 *lnh, *lnl, *wh, *wl, *a3h, *a3l, *q3, *k3, *v3;
    cudaGetSymbolAddress((void**)&qkv, g_qkv);
    cudaGetSymbolAddress((void**)&x1,  g_x1);
    cudaGetSymbolAddress((void**)&lnh, g_lnh);
    cudaGetSymbolAddress((void**)&lnl, g_lnl);
    cudaGetSymbolAddress((void**)&wh,  g_wh);
    cudaGetSymbolAddress((void**)&wl,  g_wl);
    cudaGetSymbolAddress((void**)&a3h, g_a3h);
    cudaGetSymbolAddress((void**)&a3l, g_a3l);
    cudaGetSymbolAddress((void**)&q3,  g_q3);
    cudaGetSymbolAddress((void**)&k3,  g_k3);
    cudaGetSymbolAddress((void**)&v3,  g_v3);

    cudaFuncSetAttribute(attn_hmma, cudaFuncAttributeMaxDynamicSharedMemorySize, ASMEM);
    cudaFuncSetAttribute(gemm_tc<false,false,false,true,true>,   cudaFuncAttributeMaxDynamicSharedMemorySize, GSMEM);
    cudaFuncSetAttribute(gemm_tc<true,false,true,false,false>,   cudaFuncAttributeMaxDynamicSharedMemorySize, GSMEM);
    cudaFuncSetAttribute(gemm_tc<false,true,false,false,false>,  cudaFuncAttributeMaxDynamicSharedMemorySize, GSMEM);

    // 1. lnh/lnl = bf16-split(LN1(x))
    ln_split<true><<<MROWS, 256>>>(x, ln1s, ln1b, lnh, lnl);
    // 2. qkv GEMM (bf16 triple): Q/K packed to q3/k3; V region fp32
    convert_wt<true><<<dim3(EMB / 32, 3 * EMB / 32), dim3(32, 32)>>>(w_qkv, wh, wl, EMB, 3 * EMB);
    gemm_tc<false,false,false,true,true><<<dim3(3 * EMB / 128, MROWS / 128), 128, GSMEM>>>(
        lnh, lnl, wh, wl, b_qkv, nullptr, qkv, q3, k3, 3 * EMB, EMB);
    // 3. split/transpose V only
    prep_v<<<dim3(TLEN / 64, 32), 256>>>(qkv, v3);
    // 4. x1 = x + attention
    attn_hmma<<<(TLEN / 128) * 32, 256, ASMEM>>>(q3, k3, v3, x, x1);
    // 5. lnh/lnl = fp16-split(LN2(x1))
    ln_split<false><<<MROWS, 256>>>(x1, ln2s, ln2b, lnh, lnl);
    // 6. a3h/a3l = fp16-split(relu(ln2 @ w_fc + b_fc))   (fp16 2-term GEMM)
    convert_wt<false><<<dim3(EMB / 32, HID / 32), dim3(32, 32)>>>(w_fc, wh, nullptr, EMB, HID);
    gemm_tc<true,false,true,false,false><<<dim3(HID / 128, MROWS / 128), 128, GSMEM>>>(
        lnh, lnl, wh, wh, b_fc, nullptr, nullptr, a3h, a3l, HID, EMB);
    // 7. out = x1 + fc @ w_proj + b_proj   (fp16 2-term GEMM)
    convert_wt<false><<<dim3(HID / 32, EMB / 32), dim3(32, 32)>>>(w_proj, wh, nullptr, HID, EMB);
    gemm_tc<false,true,false,false,false><<<dim3(EMB / 128, MROWS / 128), 128, GSMEM>>>(
        a3h, a3l, wh, wh, b_proj, x1, out, nullptr, nullptr, EMB, HID);
}